// round 7
// baseline (speedup 1.0000x reference)
#include <cuda_runtime.h>
#include <cuda_bf16.h>
#include <math_constants.h>
#include <cstdint>

#define Bsz  8
#define Nseq 1024
#define Cdim 1024
#define Hn   16
#define Dh   64
#define Mrows (Bsz * Nseq)
#define OQKV 3072

// ---------------------------------------------------------------------------
// Device-global scratch (allocation-free rule)
// ---------------------------------------------------------------------------
__device__ __nv_bfloat16 g_xhi[Mrows * Cdim];
__device__ __nv_bfloat16 g_xlo[Mrows * Cdim];
__device__ __nv_bfloat16 g_wqhi[OQKV * Cdim];
__device__ __nv_bfloat16 g_wqlo[OQKV * Cdim];
__device__ __nv_bfloat16 g_wphi[Cdim * Cdim];
__device__ __nv_bfloat16 g_wplo[Cdim * Cdim];
__device__ __nv_bfloat16 g_aohi[Mrows * Cdim];
__device__ __nv_bfloat16 g_aolo[Mrows * Cdim];

// Q/K/V split buffers, layout [b*H+h][n][d], d contiguous. Q pre-scaled.
__device__ __nv_bfloat16 g_qhi[Bsz * Hn * Nseq * Dh];
__device__ __nv_bfloat16 g_qlo[Bsz * Hn * Nseq * Dh];
__device__ __nv_bfloat16 g_khi[Bsz * Hn * Nseq * Dh];
__device__ __nv_bfloat16 g_klo[Bsz * Hn * Nseq * Dh];
__device__ __nv_bfloat16 g_vhi[Bsz * Hn * Nseq * Dh];
__device__ __nv_bfloat16 g_vlo[Bsz * Hn * Nseq * Dh];

// ---------------------------------------------------------------------------
// PTX helpers (base ISA: ldmatrix / mma.sync / cp.async)
// ---------------------------------------------------------------------------
__device__ __forceinline__ uint32_t s2u(const void* p) {
    uint32_t a;
    asm("{ .reg .u64 t; cvta.to.shared.u64 t, %1; cvt.u32.u64 %0, t; }"
        : "=r"(a) : "l"(p));
    return a;
}

__device__ __forceinline__ void ldsm4(uint32_t* r, uint32_t addr) {
    asm volatile("ldmatrix.sync.aligned.m8n8.x4.shared.b16 {%0,%1,%2,%3}, [%4];"
                 : "=r"(r[0]), "=r"(r[1]), "=r"(r[2]), "=r"(r[3]) : "r"(addr));
}

__device__ __forceinline__ void ldsm4t(uint32_t* r, uint32_t addr) {
    asm volatile("ldmatrix.sync.aligned.m8n8.x4.trans.shared.b16 {%0,%1,%2,%3}, [%4];"
                 : "=r"(r[0]), "=r"(r[1]), "=r"(r[2]), "=r"(r[3]) : "r"(addr));
}

__device__ __forceinline__ void mma16816(float* c, const uint32_t* a,
                                         const uint32_t* b) {
    asm volatile(
        "mma.sync.aligned.m16n8k16.row.col.f32.bf16.bf16.f32 "
        "{%0,%1,%2,%3}, {%4,%5,%6,%7}, {%8,%9}, {%0,%1,%2,%3};"
        : "+f"(c[0]), "+f"(c[1]), "+f"(c[2]), "+f"(c[3])
        : "r"(a[0]), "r"(a[1]), "r"(a[2]), "r"(a[3]), "r"(b[0]), "r"(b[1]));
}

__device__ __forceinline__ void cpa16(uint32_t saddr, const void* g) {
    asm volatile("cp.async.cg.shared.global [%0], [%1], 16;"
                 :: "r"(saddr), "l"(g));
}
#define CP_COMMIT asm volatile("cp.async.commit_group;")
#define CP_WAIT(n) asm volatile("cp.async.wait_group %0;" :: "n"(n))

__device__ __forceinline__ float ex2(float x) {
    float r;
    asm("ex2.approx.ftz.f32 %0, %1;" : "=f"(r) : "f"(x));
    return r;
}

__device__ __forceinline__ uint32_t packsplit(float a, float b, uint32_t& lo_out) {
    __nv_bfloat16 ha = __float2bfloat16_rn(a);
    __nv_bfloat16 hb = __float2bfloat16_rn(b);
    __nv_bfloat162 hp; hp.x = ha; hp.y = hb;
    __nv_bfloat162 lp = __floats2bfloat162_rn(a - __bfloat162float(ha),
                                              b - __bfloat162float(hb));
    lo_out = reinterpret_cast<uint32_t&>(lp);
    return reinterpret_cast<uint32_t&>(hp);
}

// ---------------------------------------------------------------------------
// fp32 -> (bf16 hi, bf16 lo) split pre-pass for GEMM inputs.
// ---------------------------------------------------------------------------
__global__ __launch_bounds__(256) void cvt_hilo(const float4* __restrict__ in,
                                                int which, int n4) {
    int i = blockIdx.x * blockDim.x + threadIdx.x;
    if (i >= n4) return;
    uint2* hi; uint2* lo;
    if (which == 0)      { hi = (uint2*)g_xhi;  lo = (uint2*)g_xlo;  }
    else if (which == 1) { hi = (uint2*)g_wqhi; lo = (uint2*)g_wqlo; }
    else                 { hi = (uint2*)g_wphi; lo = (uint2*)g_wplo; }
    float4 v = in[i];
    uint2 H, L;
    H.x = packsplit(v.x, v.y, L.x);
    H.y = packsplit(v.z, v.w, L.y);
    hi[i] = H;
    lo[i] = L;
}

// ---------------------------------------------------------------------------
// bf16x3 mma.sync GEMM. CTA tile 128x256, 8 warps 2x4, warp tile 64x64,
// K-chunk 16, 4-stage cp.async, one barrier per chunk.
// mode 0: split-write q/k/v (q pre-scaled);  mode 1: +bias -> out.
// ---------------------------------------------------------------------------
#define KC     16
#define PITCH  48                      // 32B data + 16B pad, ldsm conflict-free
#define AREGB  (128 * PITCH)           // 6144
#define BREGB  (256 * PITCH)           // 12288
#define STAGEB (2 * AREGB + 2 * BREGB) // 36864
#define NSTAGE 4
#define GEMM_SMEM (NSTAGE * STAGEB)    // 147456

__global__ __launch_bounds__(256, 1) void gemm_mma(int mode,
                                                   const float* __restrict__ bias,
                                                   float* __restrict__ out) {
    extern __shared__ char smem[];
    const uint32_t sb = s2u(smem);
    const int tid = threadIdx.x;
    const int m0 = blockIdx.y * 128;
    const int o0 = blockIdx.x * 256;

    const __nv_bfloat16* srcA[2] = {
        ((mode == 0) ? g_xhi  : g_aohi) + (size_t)m0 * Cdim,
        ((mode == 0) ? g_xlo  : g_aolo) + (size_t)m0 * Cdim};
    const __nv_bfloat16* srcB[2] = {
        ((mode == 0) ? g_wqhi : g_wphi) + (size_t)o0 * Cdim,
        ((mode == 0) ? g_wqlo : g_wplo) + (size_t)o0 * Cdim};

    // per chunk: A 512 + B 1024 cp.async16 over 256 threads = 6 each
    auto issue = [&](int c, int stage) {
        uint32_t s0 = sb + stage * STAGEB;
        const int ko = c * KC;
#pragma unroll
        for (int j = 0; j < 2; j++) {
            int idx = j * 256 + tid;          // 0..511
            int mt  = idx >> 8;
            int r   = (idx >> 1) & 127;
            int c8  = idx & 1;
            cpa16(s0 + mt * AREGB + r * PITCH + c8 * 16,
                  srcA[mt] + r * Cdim + ko + c8 * 8);
        }
#pragma unroll
        for (int j = 0; j < 4; j++) {
            int idx = j * 256 + tid;          // 0..1023
            int mt  = idx >> 9;
            int r   = (idx >> 1) & 255;
            int c8  = idx & 1;
            cpa16(s0 + 2 * AREGB + mt * BREGB + r * PITCH + c8 * 16,
                  srcB[mt] + r * Cdim + ko + c8 * 8);
        }
    };

    const int wid = tid >> 5, lane = tid & 31;
    const int wm = wid >> 2;   // 0..1 -> rows wm*64
    const int wn = wid & 3;    // 0..3 -> cols wn*64

    const int a_row  = wm * 64 + (lane & 15);
    const int a_colb = (lane >> 4) * 16;
    const int b_rowi = wn * 64 + ((lane >> 4) << 3) + (lane & 7);   // + ng*16
    const int b_colb = ((lane >> 3) & 1) * 16;

    float acc[4][8][4];
#pragma unroll
    for (int i = 0; i < 4; i++)
#pragma unroll
        for (int j = 0; j < 8; j++)
#pragma unroll
            for (int k = 0; k < 4; k++) acc[i][j][k] = 0.0f;

    issue(0, 0); CP_COMMIT;
    issue(1, 1); CP_COMMIT;
    issue(2, 2); CP_COMMIT;

    const int NCH = Cdim / KC;   // 64
    for (int c = 0; c < NCH; c++) {
        if (c + 2 < NCH)      { CP_WAIT(2); }
        else if (c + 1 < NCH) { CP_WAIT(1); }
        else                  { CP_WAIT(0); }
        __syncthreads();

        const uint32_t base = sb + (c & 3) * STAGEB;
        uint32_t Ah[4][4], Al[4][4];
#pragma unroll
        for (int mb = 0; mb < 4; mb++) {
            uint32_t ra = base + (a_row + mb * 16) * PITCH + a_colb;
            ldsm4(Ah[mb], ra);
            ldsm4(Al[mb], ra + AREGB);
        }
#pragma unroll
        for (int ng = 0; ng < 4; ng++) {
            uint32_t Bhf[4], Blf[4];
            uint32_t rb = base + 2 * AREGB + (b_rowi + ng * 16) * PITCH + b_colb;
            ldsm4(Bhf, rb);
            ldsm4(Blf, rb + BREGB);
#pragma unroll
            for (int mb = 0; mb < 4; mb++)
#pragma unroll
                for (int half = 0; half < 2; half++) {
                    float* a = acc[mb][ng * 2 + half];
                    mma16816(a, Ah[mb], &Bhf[half * 2]);
                    mma16816(a, Ah[mb], &Blf[half * 2]);
                    mma16816(a, Al[mb], &Bhf[half * 2]);
                }
        }
        // refill stage (c+3)&3: last read before this chunk's barrier.
        if (c + 3 < NCH) { issue(c + 3, (c + 3) & 3); CP_COMMIT; }
    }

    // Epilogue: warp rows wm*64+mb*16+(lane>>2)(+8), cols wn*64+nb*8+(lane&3)*2
    if (mode == 0) {
        const int which = o0 >> 10;   // 256-tile never crosses a 1024 boundary
        __nv_bfloat16 *hip, *lop;
        float sc;
        const float qs = 0.125f * 1.44269504088896340736f;
        if (which == 0)      { hip = g_qhi; lop = g_qlo; sc = qs; }
        else if (which == 1) { hip = g_khi; lop = g_klo; sc = 1.0f; }
        else                 { hip = g_vhi; lop = g_vlo; sc = 1.0f; }
#pragma unroll
        for (int mb = 0; mb < 4; mb++) {
            const int m = m0 + wm * 64 + mb * 16 + (lane >> 2);
            const int bb = m >> 10, n = m & 1023;
#pragma unroll
            for (int nb = 0; nb < 8; nb++) {
                const int o = o0 + wn * 64 + nb * 8 + (lane & 3) * 2;
                const int h = (o & 1023) >> 6;
                const int d = o & 63;
                size_t base = ((size_t)(bb * Hn + h) * Nseq + n) * Dh + d;
                uint32_t L0, L1;
                uint32_t H0 = packsplit(acc[mb][nb][0] * sc, acc[mb][nb][1] * sc, L0);
                uint32_t H1 = packsplit(acc[mb][nb][2] * sc, acc[mb][nb][3] * sc, L1);
                *(uint32_t*)(hip + base)          = H0;
                *(uint32_t*)(lop + base)          = L0;
                *(uint32_t*)(hip + base + 8 * Dh) = H1;
                *(uint32_t*)(lop + base + 8 * Dh) = L1;
            }
        }
    } else {
#pragma unroll
        for (int mb = 0; mb < 4; mb++) {
            const int m = m0 + wm * 64 + mb * 16 + (lane >> 2);
#pragma unroll
            for (int nb = 0; nb < 8; nb++) {
                const int o = o0 + wn * 64 + nb * 8 + (lane & 3) * 2;
                const float2 bv = *(const float2*)(bias + o);
                float* dst = out + (size_t)m * Cdim + o;
                *(float2*)dst = make_float2(acc[mb][nb][0] + bv.x,
                                            acc[mb][nb][1] + bv.y);
                *(float2*)(dst + 8 * Cdim) = make_float2(acc[mb][nb][2] + bv.x,
                                                         acc[mb][nb][3] + bv.y);
            }
        }
    }
}

// ---------------------------------------------------------------------------
// Flash attention via mma.sync bf16x3.
// CTA: 128 Q rows x one (b,h). 8 warps, 16 Q rows each. KV in 64-row tiles,
// 2-stage cp.async (108KB smem -> 2 CTAs/SM). P split in-register.
// ---------------------------------------------------------------------------
#define APITCH 144                       // 64 bf16 + 8 pad
#define AQREG  (128 * APITCH)            // 18432, Q hi/lo (128 rows)
#define AKREG  (64 * APITCH)             // 9216 per KV matrix (64 rows)
#define AKV0   (2 * AQREG)               // 36864
#define ASTAGE (4 * AKREG)               // Kh,Kl,Vh,Vl = 36864
#define ATTN_SMEM (2 * AQREG + 2 * ASTAGE)  // 110592

__global__ __launch_bounds__(256, 2) void attn_mma() {
    extern __shared__ char smem[];
    const uint32_t sb = s2u(smem);
    const int tid = threadIdx.x;
    const int w = tid >> 5, lane = tid & 31;
    const int bh = blockIdx.x;           // 0..127
    const int qb = blockIdx.y;           // 0..7

    const size_t hoff = (size_t)bh * (Nseq * Dh);
    const __nv_bfloat16* qh = g_qhi + hoff + (size_t)qb * 128 * Dh;
    const __nv_bfloat16* ql = g_qlo + hoff + (size_t)qb * 128 * Dh;

    auto loadQ = [&]() {
#pragma unroll
        for (int j = 0; j < 8; j++) {
            int idx = j * 256 + tid;          // 0..2047
            int mt  = idx >> 10;              // 0=hi 1=lo
            int r   = (idx >> 3) & 127;
            int c8  = idx & 7;
            const __nv_bfloat16* src = mt ? ql : qh;
            cpa16(sb + mt * AQREG + r * APITCH + c8 * 16, src + r * Dh + c8 * 8);
        }
    };
    auto loadKV = [&](int kb, int st) {     // kb: 64-row block id 0..15
        const size_t koff = hoff + (size_t)kb * 64 * Dh;
        const __nv_bfloat16* srcs[4] = {g_khi + koff, g_klo + koff,
                                        g_vhi + koff, g_vlo + koff};
        uint32_t base = sb + AKV0 + st * ASTAGE;
#pragma unroll
        for (int j = 0; j < 8; j++) {
            int idx = j * 256 + tid;          // 0..2047
            int mt  = idx >> 9;               // matrix 0..3
            int r   = (idx >> 3) & 63;
            int c8  = idx & 7;
            cpa16(base + mt * AKREG + r * APITCH + c8 * 16,
                  srcs[mt] + r * Dh + c8 * 8);
        }
    };

    loadQ();          CP_COMMIT;
    loadKV(0, 0);     CP_COMMIT;
    loadKV(1, 1);     CP_COMMIT;

    const int a_rowb = (w * 16 + (lane & 15)) * APITCH + (lane >> 4) * 16;
    const int k_rowi = ((lane >> 4) << 3) + (lane & 7);      // + ng*16
    const int k_colb = ((lane >> 3) & 1) * 16;               // + kc*32
    const int v_rowi = (lane & 7) + ((lane >> 3) & 1) * 8;   // + kc2*16
    const int v_colb = (lane >> 4) * 16;                     // + dg*32

    CP_WAIT(2);       // Q resident
    __syncthreads();

    uint32_t QAh[4][4];
#pragma unroll
    for (int kc = 0; kc < 4; kc++)
        ldsm4(QAh[kc], sb + a_rowb + kc * 32);

    float O[8][4];
#pragma unroll
    for (int i = 0; i < 8; i++)
#pragma unroll
        for (int j = 0; j < 4; j++) O[i][j] = 0.0f;
    float m0 = -1e30f, m1 = -1e30f;
    float l0 = 0.0f, l1 = 0.0f;

    for (int kb = 0; kb < 16; kb++) {
        if (kb + 1 < 16) { CP_WAIT(1); } else { CP_WAIT(0); }
        __syncthreads();
        const uint32_t kbase = sb + AKV0 + (kb & 1) * ASTAGE;

        // Q-lo frags from smem (saves 16 persistent regs)
        uint32_t QAl[4][4];
#pragma unroll
        for (int kc = 0; kc < 4; kc++)
            ldsm4(QAl[kc], sb + AQREG + a_rowb + kc * 32);

        // ----- S = Q K^T (3 passes), 64 cols = 4 n-groups ------------------
        float S[8][4];
#pragma unroll
        for (int i = 0; i < 8; i++)
#pragma unroll
            for (int j = 0; j < 4; j++) S[i][j] = 0.0f;

#pragma unroll
        for (int ng = 0; ng < 4; ng++) {
#pragma unroll
            for (int kc = 0; kc < 4; kc++) {
                uint32_t kbh[4], kbl[4];
                uint32_t rb = kbase + (ng * 16 + k_rowi) * APITCH
                            + k_colb + kc * 32;
                ldsm4(kbh, rb);
                ldsm4(kbl, rb + AKREG);
#pragma unroll
                for (int half = 0; half < 2; half++) {
                    float* s = S[ng * 2 + half];
                    mma16816(s, QAh[kc], &kbh[half * 2]);
                    mma16816(s, QAh[kc], &kbl[half * 2]);
                    mma16816(s, QAl[kc], &kbh[half * 2]);
                }
            }
        }

        // ----- online softmax ---------------------------------------------
        float rm0 = -1e30f, rm1 = -1e30f;
#pragma unroll
        for (int i = 0; i < 8; i++) {
            rm0 = fmaxf(rm0, fmaxf(S[i][0], S[i][1]));
            rm1 = fmaxf(rm1, fmaxf(S[i][2], S[i][3]));
        }
        rm0 = fmaxf(rm0, __shfl_xor_sync(0xffffffffu, rm0, 1));
        rm0 = fmaxf(rm0, __shfl_xor_sync(0xffffffffu, rm0, 2));
        rm1 = fmaxf(rm1, __shfl_xor_sync(0xffffffffu, rm1, 1));
        rm1 = fmaxf(rm1, __shfl_xor_sync(0xffffffffu, rm1, 2));

        float mn0 = fmaxf(m0, rm0), mn1 = fmaxf(m1, rm1);
        float al0 = ex2(m0 - mn0),  al1 = ex2(m1 - mn1);
        m0 = mn0; m1 = mn1;
        l0 *= al0; l1 *= al1;
#pragma unroll
        for (int i = 0; i < 8; i++) {
            O[i][0] *= al0; O[i][1] *= al0;
            O[i][2] *= al1; O[i][3] *= al1;
        }
        float ps0 = 0.0f, ps1 = 0.0f;
#pragma unroll
        for (int i = 0; i < 8; i++) {
            S[i][0] = ex2(S[i][0] - mn0);
            S[i][1] = ex2(S[i][1] - mn0);
            S[i][2] = ex2(S[i][2] - mn1);
            S[i][3] = ex2(S[i][3] - mn1);
            ps0 += S[i][0] + S[i][1];
            ps1 += S[i][2] + S[i][3];
        }
        l0 += ps0; l1 += ps1;

        // ----- O += P V (3 passes), 64 KV rows = 4 k-chunks ----------------
#pragma unroll
        for (int kc2 = 0; kc2 < 4; kc2++) {
            uint32_t pah[4], pal[4];
            pah[0] = packsplit(S[2 * kc2][0],     S[2 * kc2][1],     pal[0]);
            pah[1] = packsplit(S[2 * kc2][2],     S[2 * kc2][3],     pal[1]);
            pah[2] = packsplit(S[2 * kc2 + 1][0], S[2 * kc2 + 1][1], pal[2]);
            pah[3] = packsplit(S[2 * kc2 + 1][2], S[2 * kc2 + 1][3], pal[3]);
#pragma unroll
            for (int dg = 0; dg < 4; dg++) {
                uint32_t vbh[4], vbl[4];
                uint32_t rv = kbase + 2 * AKREG
                            + (kc2 * 16 + v_rowi) * APITCH + v_colb + dg * 32;
                ldsm4t(vbh, rv);
                ldsm4t(vbl, rv + AKREG);
#pragma unroll
                for (int half = 0; half < 2; half++) {
                    float* o = O[dg * 2 + half];
                    mma16816(o, pah, &vbh[half * 2]);
                    mma16816(o, pah, &vbl[half * 2]);
                    mma16816(o, pal, &vbh[half * 2]);
                }
            }
        }

        __syncthreads();
        if (kb + 2 < 16) { loadKV(kb + 2, kb & 1); CP_COMMIT; }
    }

    // ----- finalize + write bf16 hi/lo for proj GEMM -----------------------
    l0 += __shfl_xor_sync(0xffffffffu, l0, 1);
    l0 += __shfl_xor_sync(0xffffffffu, l0, 2);
    l1 += __shfl_xor_sync(0xffffffffu, l1, 1);
    l1 += __shfl_xor_sync(0xffffffffu, l1, 2);
    const float inv0 = 1.0f / l0, inv1 = 1.0f / l1;

    const int b = bh >> 4, h = bh & 15;
    const int n0 = qb * 128 + w * 16 + (lane >> 2);
#pragma unroll
    for (int nb = 0; nb < 8; nb++) {
        const int d = nb * 8 + (lane & 3) * 2;
        size_t base0 = ((size_t)(b * Nseq + n0) * Cdim) + h * Dh + d;
        size_t base1 = base0 + (size_t)8 * Cdim;
        uint32_t L0, L1;
        uint32_t H0 = packsplit(O[nb][0] * inv0, O[nb][1] * inv0, L0);
        uint32_t H1 = packsplit(O[nb][2] * inv1, O[nb][3] * inv1, L1);
        *(uint32_t*)(g_aohi + base0) = H0;
        *(uint32_t*)(g_aolo + base0) = L0;
        *(uint32_t*)(g_aohi + base1) = H1;
        *(uint32_t*)(g_aolo + base1) = L1;
    }
}

// ---------------------------------------------------------------------------
extern "C" void kernel_launch(void* const* d_in, const int* in_sizes, int n_in,
                              void* d_out, int out_size) {
    const float* x      = (const float*)d_in[0];   // [8,1024,1024]
    const float* w_qkv  = (const float*)d_in[1];   // [3072,1024]
    const float* w_proj = (const float*)d_in[2];   // [1024,1024]
    const float* b_proj = (const float*)d_in[3];   // [1024]
    float* out = (float*)d_out;

    cudaFuncSetAttribute(gemm_mma,
                         cudaFuncAttributeMaxDynamicSharedMemorySize, GEMM_SMEM);
    cudaFuncSetAttribute(attn_mma,
                         cudaFuncAttributeMaxDynamicSharedMemorySize, ATTN_SMEM);

    {
        int n4 = (Mrows * Cdim) / 4;
        cvt_hilo<<<(n4 + 255) / 256, 256>>>((const float4*)x, 0, n4);
    }
    {
        int n4 = (OQKV * Cdim) / 4;
        cvt_hilo<<<(n4 + 255) / 256, 256>>>((const float4*)w_qkv, 1, n4);
    }
    {
        int n4 = (Cdim * Cdim) / 4;
        cvt_hilo<<<(n4 + 255) / 256, 256>>>((const float4*)w_proj, 2, n4);
    }

    dim3 g1(OQKV / 256, Mrows / 128);              // (12, 64)
    gemm_mma<<<g1, 256, GEMM_SMEM>>>(0, nullptr, nullptr);

    dim3 g2(Bsz * Hn, Nseq / 128);                 // (128, 8)
    attn_mma<<<g2, 256, ATTN_SMEM>>>();

    dim3 g3(Cdim / 256, Mrows / 128);              // (4, 64)
    gemm_mma<<<g3, 256, GEMM_SMEM>>>(1, b_proj, out);
}

// round 8
// speedup vs baseline: 1.0833x; 1.0833x over previous
#include <cuda_runtime.h>
#include <cuda_bf16.h>
#include <math_constants.h>
#include <cstdint>

#define Bsz  8
#define Nseq 1024
#define Cdim 1024
#define Hn   16
#define Dh   64
#define Mrows (Bsz * Nseq)
#define OQKV 3072

// ---------------------------------------------------------------------------
// Device-global scratch (allocation-free rule)
// ---------------------------------------------------------------------------
__device__ __nv_bfloat16 g_xhi[Mrows * Cdim];
__device__ __nv_bfloat16 g_xlo[Mrows * Cdim];
__device__ __nv_bfloat16 g_wqhi[OQKV * Cdim];
__device__ __nv_bfloat16 g_wqlo[OQKV * Cdim];
__device__ __nv_bfloat16 g_wphi[Cdim * Cdim];
__device__ __nv_bfloat16 g_wplo[Cdim * Cdim];
__device__ __nv_bfloat16 g_aohi[Mrows * Cdim];
__device__ __nv_bfloat16 g_aolo[Mrows * Cdim];

// Q/K/V split buffers, layout [b*H+h][n][d], d contiguous. Q pre-scaled.
__device__ __nv_bfloat16 g_qhi[Bsz * Hn * Nseq * Dh];
__device__ __nv_bfloat16 g_qlo[Bsz * Hn * Nseq * Dh];
__device__ __nv_bfloat16 g_khi[Bsz * Hn * Nseq * Dh];
__device__ __nv_bfloat16 g_klo[Bsz * Hn * Nseq * Dh];
__device__ __nv_bfloat16 g_vhi[Bsz * Hn * Nseq * Dh];
__device__ __nv_bfloat16 g_vlo[Bsz * Hn * Nseq * Dh];

// ---------------------------------------------------------------------------
// PTX helpers (base ISA: ldmatrix / mma.sync / cp.async)
// ---------------------------------------------------------------------------
__device__ __forceinline__ uint32_t s2u(const void* p) {
    uint32_t a;
    asm("{ .reg .u64 t; cvta.to.shared.u64 t, %1; cvt.u32.u64 %0, t; }"
        : "=r"(a) : "l"(p));
    return a;
}

__device__ __forceinline__ void ldsm4(uint32_t* r, uint32_t addr) {
    asm volatile("ldmatrix.sync.aligned.m8n8.x4.shared.b16 {%0,%1,%2,%3}, [%4];"
                 : "=r"(r[0]), "=r"(r[1]), "=r"(r[2]), "=r"(r[3]) : "r"(addr));
}

__device__ __forceinline__ void ldsm4t(uint32_t* r, uint32_t addr) {
    asm volatile("ldmatrix.sync.aligned.m8n8.x4.trans.shared.b16 {%0,%1,%2,%3}, [%4];"
                 : "=r"(r[0]), "=r"(r[1]), "=r"(r[2]), "=r"(r[3]) : "r"(addr));
}

__device__ __forceinline__ void mma16816(float* c, const uint32_t* a,
                                         const uint32_t* b) {
    asm volatile(
        "mma.sync.aligned.m16n8k16.row.col.f32.bf16.bf16.f32 "
        "{%0,%1,%2,%3}, {%4,%5,%6,%7}, {%8,%9}, {%0,%1,%2,%3};"
        : "+f"(c[0]), "+f"(c[1]), "+f"(c[2]), "+f"(c[3])
        : "r"(a[0]), "r"(a[1]), "r"(a[2]), "r"(a[3]), "r"(b[0]), "r"(b[1]));
}

__device__ __forceinline__ void cpa16(uint32_t saddr, const void* g) {
    asm volatile("cp.async.cg.shared.global [%0], [%1], 16;"
                 :: "r"(saddr), "l"(g));
}
#define CP_COMMIT asm volatile("cp.async.commit_group;")
#define CP_WAIT(n) asm volatile("cp.async.wait_group %0;" :: "n"(n))

__device__ __forceinline__ float ex2(float x) {
    float r;
    asm("ex2.approx.ftz.f32 %0, %1;" : "=f"(r) : "f"(x));
    return r;
}

__device__ __forceinline__ uint32_t packsplit(float a, float b, uint32_t& lo_out) {
    __nv_bfloat16 ha = __float2bfloat16_rn(a);
    __nv_bfloat16 hb = __float2bfloat16_rn(b);
    __nv_bfloat162 hp; hp.x = ha; hp.y = hb;
    __nv_bfloat162 lp = __floats2bfloat162_rn(a - __bfloat162float(ha),
                                              b - __bfloat162float(hb));
    lo_out = reinterpret_cast<uint32_t&>(lp);
    return reinterpret_cast<uint32_t&>(hp);
}

// ---------------------------------------------------------------------------
// fp32 -> (bf16 hi, bf16 lo) split pre-pass, single merged launch.
// Layout of work: [0, X4) -> x, [X4, X4+WQ4) -> w_qkv, rest -> w_proj.
// ---------------------------------------------------------------------------
#define X4  ((Mrows * Cdim) / 4)
#define WQ4 ((OQKV * Cdim) / 4)
#define WP4 ((Cdim * Cdim) / 4)

__global__ __launch_bounds__(256) void cvt_all(const float4* __restrict__ x,
                                               const float4* __restrict__ wq,
                                               const float4* __restrict__ wp) {
    int i = blockIdx.x * blockDim.x + threadIdx.x;
    const float4* in;
    uint2 *hi, *lo;
    int j;
    if (i < X4) {
        in = x; j = i;
        hi = (uint2*)g_xhi; lo = (uint2*)g_xlo;
    } else if (i < X4 + WQ4) {
        in = wq; j = i - X4;
        hi = (uint2*)g_wqhi; lo = (uint2*)g_wqlo;
    } else if (i < X4 + WQ4 + WP4) {
        in = wp; j = i - X4 - WQ4;
        hi = (uint2*)g_wphi; lo = (uint2*)g_wplo;
    } else return;
    float4 v = in[j];
    uint2 H, L;
    H.x = packsplit(v.x, v.y, L.x);
    H.y = packsplit(v.z, v.w, L.y);
    hi[j] = H;
    lo[j] = L;
}

// ---------------------------------------------------------------------------
// bf16x3 mma.sync GEMM. CTA 128x128, 8 warps (64x32 each), K-chunk 16,
// 4-stage cp.async, one barrier per chunk, 2 CTAs/SM.
// Inner loop = 3 separate passes (hh, hl, lh) over all 16 accs so consecutive
// writes to one acc are 16 HMMAs apart (no dependency stalls).
// ---------------------------------------------------------------------------
#define KC    16
#define PITCH 48                       // 32B data + 16B pad, ldsm conflict-free
#define REGB  (128 * PITCH)            // 6144
#define BUFB  (4 * REGB)               // 24576 per stage
#define NSTAGE 4
#define GEMM_SMEM (NSTAGE * BUFB)      // 98304

__global__ __launch_bounds__(256, 2) void gemm_mma(int mode,
                                                   const float* __restrict__ bias,
                                                   float* __restrict__ out) {
    extern __shared__ char smem[];
    const uint32_t sb = s2u(smem);
    const int tid = threadIdx.x;
    const int m0 = blockIdx.y * 128;
    const int o0 = blockIdx.x * 128;

    const __nv_bfloat16* Ahi = ((mode == 0) ? g_xhi  : g_aohi) + (size_t)m0 * Cdim;
    const __nv_bfloat16* Alo = ((mode == 0) ? g_xlo  : g_aolo) + (size_t)m0 * Cdim;
    const __nv_bfloat16* Bhi = ((mode == 0) ? g_wqhi : g_wphi) + (size_t)o0 * Cdim;
    const __nv_bfloat16* Blo = ((mode == 0) ? g_wqlo : g_wplo) + (size_t)o0 * Cdim;
    const __nv_bfloat16* srcs[4] = {Ahi, Alo, Bhi, Blo};

    auto issue = [&](int c, int stage) {
        uint32_t s0 = sb + stage * BUFB;
        const int ko = c * KC;
#pragma unroll
        for (int j = 0; j < 4; j++) {
            int idx = j * 256 + tid;      // 0..1023
            int mt  = idx >> 8;
            int r   = (idx >> 1) & 127;
            int c8  = idx & 1;
            cpa16(s0 + mt * REGB + r * PITCH + c8 * 16,
                  srcs[mt] + r * Cdim + ko + c8 * 8);
        }
    };

    const int wid = tid >> 5, lane = tid & 31;
    const int wm = wid >> 2;
    const int wn = wid & 3;

    const int a_row  = wm * 64 + (lane & 15);
    const int a_colb = (lane >> 4) * 16;
    const int b_row  = wn * 32 + ((lane >> 4) << 3) + (lane & 7);
    const int b_colb = ((lane >> 3) & 1) * 16;

    float acc[4][4][4];
#pragma unroll
    for (int i = 0; i < 4; i++)
#pragma unroll
        for (int j = 0; j < 4; j++)
#pragma unroll
            for (int k = 0; k < 4; k++) acc[i][j][k] = 0.0f;

    issue(0, 0); CP_COMMIT;
    issue(1, 1); CP_COMMIT;
    issue(2, 2); CP_COMMIT;

    const int NCH = Cdim / KC;   // 64
    for (int c = 0; c < NCH; c++) {
        if (c + 2 < NCH)      { CP_WAIT(2); }
        else if (c + 1 < NCH) { CP_WAIT(1); }
        else                  { CP_WAIT(0); }
        __syncthreads();

        const uint32_t base = sb + (c & 3) * BUFB;
        uint32_t Ah[4][4], Al[4][4], Bh[2][4], Bl[2][4];
#pragma unroll
        for (int mb = 0; mb < 4; mb++) {
            uint32_t ra = base + (a_row + mb * 16) * PITCH + a_colb;
            ldsm4(Ah[mb], ra);
            ldsm4(Al[mb], ra + REGB);
        }
#pragma unroll
        for (int nbp = 0; nbp < 2; nbp++) {
            uint32_t rb = base + 2 * REGB + (b_row + nbp * 16) * PITCH + b_colb;
            ldsm4(Bh[nbp], rb);
            ldsm4(Bl[nbp], rb + REGB);
        }
        // pass 1: hi*hi over all 16 accs (independent chains)
#pragma unroll
        for (int mb = 0; mb < 4; mb++)
#pragma unroll
            for (int nb = 0; nb < 4; nb++)
                mma16816(acc[mb][nb], Ah[mb], &Bh[nb >> 1][(nb & 1) * 2]);
        // pass 2: hi*lo
#pragma unroll
        for (int mb = 0; mb < 4; mb++)
#pragma unroll
            for (int nb = 0; nb < 4; nb++)
                mma16816(acc[mb][nb], Ah[mb], &Bl[nb >> 1][(nb & 1) * 2]);
        // pass 3: lo*hi
#pragma unroll
        for (int mb = 0; mb < 4; mb++)
#pragma unroll
            for (int nb = 0; nb < 4; nb++)
                mma16816(acc[mb][nb], Al[mb], &Bh[nb >> 1][(nb & 1) * 2]);

        if (c + 3 < NCH) { issue(c + 3, (c + 3) & 3); CP_COMMIT; }
    }

    const int erow = m0 + wm * 64 + (lane >> 2);
    const int ecol = o0 + wn * 32 + (lane & 3) * 2;
    if (mode == 0) {
        const int which = o0 >> 10;
        __nv_bfloat16 *hip, *lop;
        float sc;
        const float qs = 0.125f * 1.44269504088896340736f;
        if (which == 0)      { hip = g_qhi; lop = g_qlo; sc = qs; }
        else if (which == 1) { hip = g_khi; lop = g_klo; sc = 1.0f; }
        else                 { hip = g_vhi; lop = g_vlo; sc = 1.0f; }
#pragma unroll
        for (int mb = 0; mb < 4; mb++) {
            const int m = erow + mb * 16;
            const int bb = m >> 10, n = m & 1023;
#pragma unroll
            for (int nb = 0; nb < 4; nb++) {
                const int o = ecol + nb * 8;
                const int h = (o & 1023) >> 6;
                const int d = o & 63;
                size_t base = ((size_t)(bb * Hn + h) * Nseq + n) * Dh + d;
                uint32_t L0, L1;
                uint32_t H0 = packsplit(acc[mb][nb][0] * sc, acc[mb][nb][1] * sc, L0);
                uint32_t H1 = packsplit(acc[mb][nb][2] * sc, acc[mb][nb][3] * sc, L1);
                *(uint32_t*)(hip + base)            = H0;
                *(uint32_t*)(lop + base)            = L0;
                *(uint32_t*)(hip + base + 8 * Dh)   = H1;
                *(uint32_t*)(lop + base + 8 * Dh)   = L1;
            }
        }
    } else {
#pragma unroll
        for (int mb = 0; mb < 4; mb++) {
            const int m = erow + mb * 16;
#pragma unroll
            for (int nb = 0; nb < 4; nb++) {
                const int o = ecol + nb * 8;
                const float2 bv = *(const float2*)(bias + o);
                float* dst = out + (size_t)m * Cdim + o;
                *(float2*)dst = make_float2(acc[mb][nb][0] + bv.x,
                                            acc[mb][nb][1] + bv.y);
                *(float2*)(dst + 8 * Cdim) = make_float2(acc[mb][nb][2] + bv.x,
                                                         acc[mb][nb][3] + bv.y);
            }
        }
    }
}

// ---------------------------------------------------------------------------
// Flash attention via mma.sync bf16x3.
// CTA: 128 Q rows x one (b,h). 8 warps, 16 Q rows each. KV in 64-row tiles,
// 2-stage cp.async (108KB smem -> 2 CTAs/SM). P split in-register.
// ---------------------------------------------------------------------------
#define APITCH 144                       // 64 bf16 + 8 pad
#define AQREG  (128 * APITCH)            // 18432, Q hi/lo (128 rows)
#define AKREG  (64 * APITCH)             // 9216 per KV matrix (64 rows)
#define AKV0   (2 * AQREG)               // 36864
#define ASTAGE (4 * AKREG)               // Kh,Kl,Vh,Vl = 36864
#define ATTN_SMEM (2 * AQREG + 2 * ASTAGE)  // 110592

__global__ __launch_bounds__(256, 2) void attn_mma() {
    extern __shared__ char smem[];
    const uint32_t sb = s2u(smem);
    const int tid = threadIdx.x;
    const int w = tid >> 5, lane = tid & 31;
    const int bh = blockIdx.x;           // 0..127
    const int qb = blockIdx.y;           // 0..7

    const size_t hoff = (size_t)bh * (Nseq * Dh);
    const __nv_bfloat16* qh = g_qhi + hoff + (size_t)qb * 128 * Dh;
    const __nv_bfloat16* ql = g_qlo + hoff + (size_t)qb * 128 * Dh;

    auto loadQ = [&]() {
#pragma unroll
        for (int j = 0; j < 8; j++) {
            int idx = j * 256 + tid;          // 0..2047
            int mt  = idx >> 10;              // 0=hi 1=lo
            int r   = (idx >> 3) & 127;
            int c8  = idx & 7;
            const __nv_bfloat16* src = mt ? ql : qh;
            cpa16(sb + mt * AQREG + r * APITCH + c8 * 16, src + r * Dh + c8 * 8);
        }
    };
    auto loadKV = [&](int kb, int st) {     // kb: 64-row block id 0..15
        const size_t koff = hoff + (size_t)kb * 64 * Dh;
        const __nv_bfloat16* srcs[4] = {g_khi + koff, g_klo + koff,
                                        g_vhi + koff, g_vlo + koff};
        uint32_t base = sb + AKV0 + st * ASTAGE;
#pragma unroll
        for (int j = 0; j < 8; j++) {
            int idx = j * 256 + tid;          // 0..2047
            int mt  = idx >> 9;               // matrix 0..3
            int r   = (idx >> 3) & 63;
            int c8  = idx & 7;
            cpa16(base + mt * AKREG + r * APITCH + c8 * 16,
                  srcs[mt] + r * Dh + c8 * 8);
        }
    };

    loadQ();          CP_COMMIT;
    loadKV(0, 0);     CP_COMMIT;
    loadKV(1, 1);     CP_COMMIT;

    const int a_rowb = (w * 16 + (lane & 15)) * APITCH + (lane >> 4) * 16;
    const int k_rowi = ((lane >> 4) << 3) + (lane & 7);      // + ng*16
    const int k_colb = ((lane >> 3) & 1) * 16;               // + kc*32
    const int v_rowi = (lane & 7) + ((lane >> 3) & 1) * 8;   // + kc2*16
    const int v_colb = (lane >> 4) * 16;                     // + dg*32

    CP_WAIT(2);       // Q resident
    __syncthreads();

    uint32_t QAh[4][4];
#pragma unroll
    for (int kc = 0; kc < 4; kc++)
        ldsm4(QAh[kc], sb + a_rowb + kc * 32);

    float O[8][4];
#pragma unroll
    for (int i = 0; i < 8; i++)
#pragma unroll
        for (int j = 0; j < 4; j++) O[i][j] = 0.0f;
    float m0 = -1e30f, m1 = -1e30f;
    float l0 = 0.0f, l1 = 0.0f;

    for (int kb = 0; kb < 16; kb++) {
        if (kb + 1 < 16) { CP_WAIT(1); } else { CP_WAIT(0); }
        __syncthreads();
        const uint32_t kbase = sb + AKV0 + (kb & 1) * ASTAGE;

        // Q-lo frags from smem (saves 16 persistent regs)
        uint32_t QAl[4][4];
#pragma unroll
        for (int kc = 0; kc < 4; kc++)
            ldsm4(QAl[kc], sb + AQREG + a_rowb + kc * 32);

        // ----- S = Q K^T (3 passes), 64 cols = 4 n-groups ------------------
        float S[8][4];
#pragma unroll
        for (int i = 0; i < 8; i++)
#pragma unroll
            for (int j = 0; j < 4; j++) S[i][j] = 0.0f;

#pragma unroll
        for (int ng = 0; ng < 4; ng++) {
#pragma unroll
            for (int kc = 0; kc < 4; kc++) {
                uint32_t kbh[4], kbl[4];
                uint32_t rb = kbase + (ng * 16 + k_rowi) * APITCH
                            + k_colb + kc * 32;
                ldsm4(kbh, rb);
                ldsm4(kbl, rb + AKREG);
#pragma unroll
                for (int half = 0; half < 2; half++) {
                    float* s = S[ng * 2 + half];
                    mma16816(s, QAh[kc], &kbh[half * 2]);
                    mma16816(s, QAh[kc], &kbl[half * 2]);
                    mma16816(s, QAl[kc], &kbh[half * 2]);
                }
            }
        }

        // ----- online softmax ---------------------------------------------
        float rm0 = -1e30f, rm1 = -1e30f;
#pragma unroll
        for (int i = 0; i < 8; i++) {
            rm0 = fmaxf(rm0, fmaxf(S[i][0], S[i][1]));
            rm1 = fmaxf(rm1, fmaxf(S[i][2], S[i][3]));
        }
        rm0 = fmaxf(rm0, __shfl_xor_sync(0xffffffffu, rm0, 1));
        rm0 = fmaxf(rm0, __shfl_xor_sync(0xffffffffu, rm0, 2));
        rm1 = fmaxf(rm1, __shfl_xor_sync(0xffffffffu, rm1, 1));
        rm1 = fmaxf(rm1, __shfl_xor_sync(0xffffffffu, rm1, 2));

        float mn0 = fmaxf(m0, rm0), mn1 = fmaxf(m1, rm1);
        float al0 = ex2(m0 - mn0),  al1 = ex2(m1 - mn1);
        m0 = mn0; m1 = mn1;
        l0 *= al0; l1 *= al1;
#pragma unroll
        for (int i = 0; i < 8; i++) {
            O[i][0] *= al0; O[i][1] *= al0;
            O[i][2] *= al1; O[i][3] *= al1;
        }
        float ps0 = 0.0f, ps1 = 0.0f;
#pragma unroll
        for (int i = 0; i < 8; i++) {
            S[i][0] = ex2(S[i][0] - mn0);
            S[i][1] = ex2(S[i][1] - mn0);
            S[i][2] = ex2(S[i][2] - mn1);
            S[i][3] = ex2(S[i][3] - mn1);
            ps0 += S[i][0] + S[i][1];
            ps1 += S[i][2] + S[i][3];
        }
        l0 += ps0; l1 += ps1;

        // ----- O += P V (3 passes), 64 KV rows = 4 k-chunks ----------------
#pragma unroll
        for (int kc2 = 0; kc2 < 4; kc2++) {
            uint32_t pah[4], pal[4];
            pah[0] = packsplit(S[2 * kc2][0],     S[2 * kc2][1],     pal[0]);
            pah[1] = packsplit(S[2 * kc2][2],     S[2 * kc2][3],     pal[1]);
            pah[2] = packsplit(S[2 * kc2 + 1][0], S[2 * kc2 + 1][1], pal[2]);
            pah[3] = packsplit(S[2 * kc2 + 1][2], S[2 * kc2 + 1][3], pal[3]);
#pragma unroll
            for (int dg = 0; dg < 4; dg++) {
                uint32_t vbh[4], vbl[4];
                uint32_t rv = kbase + 2 * AKREG
                            + (kc2 * 16 + v_rowi) * APITCH + v_colb + dg * 32;
                ldsm4t(vbh, rv);
                ldsm4t(vbl, rv + AKREG);
#pragma unroll
                for (int half = 0; half < 2; half++) {
                    float* o = O[dg * 2 + half];
                    mma16816(o, pah, &vbh[half * 2]);
                    mma16816(o, pah, &vbl[half * 2]);
                    mma16816(o, pal, &vbh[half * 2]);
                }
            }
        }

        __syncthreads();
        if (kb + 2 < 16) { loadKV(kb + 2, kb & 1); CP_COMMIT; }
    }

    // ----- finalize + write bf16 hi/lo for proj GEMM -----------------------
    l0 += __shfl_xor_sync(0xffffffffu, l0, 1);
    l0 += __shfl_xor_sync(0xffffffffu, l0, 2);
    l1 += __shfl_xor_sync(0xffffffffu, l1, 1);
    l1 += __shfl_xor_sync(0xffffffffu, l1, 2);
    const float inv0 = 1.0f / l0, inv1 = 1.0f / l1;

    const int b = bh >> 4, h = bh & 15;
    const int n0 = qb * 128 + w * 16 + (lane >> 2);
#pragma unroll
    for (int nb = 0; nb < 8; nb++) {
        const int d = nb * 8 + (lane & 3) * 2;
        size_t base0 = ((size_t)(b * Nseq + n0) * Cdim) + h * Dh + d;
        size_t base1 = base0 + (size_t)8 * Cdim;
        uint32_t L0, L1;
        uint32_t H0 = packsplit(O[nb][0] * inv0, O[nb][1] * inv0, L0);
        uint32_t H1 = packsplit(O[nb][2] * inv1, O[nb][3] * inv1, L1);
        *(uint32_t*)(g_aohi + base0) = H0;
        *(uint32_t*)(g_aolo + base0) = L0;
        *(uint32_t*)(g_aohi + base1) = H1;
        *(uint32_t*)(g_aolo + base1) = L1;
    }
}

// ---------------------------------------------------------------------------
extern "C" void kernel_launch(void* const* d_in, const int* in_sizes, int n_in,
                              void* d_out, int out_size) {
    const float* x      = (const float*)d_in[0];   // [8,1024,1024]
    const float* w_qkv  = (const float*)d_in[1];   // [3072,1024]
    const float* w_proj = (const float*)d_in[2];   // [1024,1024]
    const float* b_proj = (const float*)d_in[3];   // [1024]
    float* out = (float*)d_out;

    cudaFuncSetAttribute(gemm_mma,
                         cudaFuncAttributeMaxDynamicSharedMemorySize, GEMM_SMEM);
    cudaFuncSetAttribute(attn_mma,
                         cudaFuncAttributeMaxDynamicSharedMemorySize, ATTN_SMEM);

    {
        int n4 = X4 + WQ4 + WP4;
        cvt_all<<<(n4 + 255) / 256, 256>>>((const float4*)x,
                                           (const float4*)w_qkv,
                                           (const float4*)w_proj);
    }

    dim3 g1(OQKV / 128, Mrows / 128);              // (24, 64)
    gemm_mma<<<g1, 256, GEMM_SMEM>>>(0, nullptr, nullptr);

    dim3 g2(Bsz * Hn, Nseq / 128);                 // (128, 8)
    attn_mma<<<g2, 256, ATTN_SMEM>>>();

    dim3 g3(Cdim / 128, Mrows / 128);              // (8, 64)
    gemm_mma<<<g3, 256, GEMM_SMEM>>>(1, b_proj, out);
}

// round 10
// speedup vs baseline: 1.2362x; 1.1411x over previous
#include <cuda_runtime.h>
#include <cuda_bf16.h>
#include <cuda_fp16.h>
#include <math_constants.h>
#include <cstdint>

#define Bsz  8
#define Nseq 1024
#define Cdim 1024
#define Hn   16
#define Dh   64
#define Mrows (Bsz * Nseq)
#define OQKV 3072

// ---------------------------------------------------------------------------
// Device-global scratch (allocation-free rule)
// ---------------------------------------------------------------------------
__device__ __half g_xh[Mrows * Cdim];          // x fp16 hi
__device__ __half g_xl[Mrows * Cdim];          // x fp16 lo
__device__ __half g_wq[OQKV * Cdim];           // w_qkv fp16 single
__device__ __nv_bfloat16 g_wphi[Cdim * Cdim];  // w_proj bf16 hi/lo
__device__ __nv_bfloat16 g_wplo[Cdim * Cdim];
__device__ __nv_bfloat16 g_aohi[Mrows * Cdim]; // attention out bf16 hi/lo
__device__ __nv_bfloat16 g_aolo[Mrows * Cdim];

// Q/K/V bf16 split buffers, layout [b*H+h][n][d], d contiguous. Q pre-scaled.
__device__ __nv_bfloat16 g_qhi[Bsz * Hn * Nseq * Dh];
__device__ __nv_bfloat16 g_qlo[Bsz * Hn * Nseq * Dh];
__device__ __nv_bfloat16 g_khi[Bsz * Hn * Nseq * Dh];
__device__ __nv_bfloat16 g_klo[Bsz * Hn * Nseq * Dh];
__device__ __nv_bfloat16 g_vhi[Bsz * Hn * Nseq * Dh];
__device__ __nv_bfloat16 g_vlo[Bsz * Hn * Nseq * Dh];

// ---------------------------------------------------------------------------
// PTX helpers (base ISA: ldmatrix / mma.sync / cp.async)
// ---------------------------------------------------------------------------
__device__ __forceinline__ uint32_t s2u(const void* p) {
    uint32_t a;
    asm("{ .reg .u64 t; cvta.to.shared.u64 t, %1; cvt.u32.u64 %0, t; }"
        : "=r"(a) : "l"(p));
    return a;
}

__device__ __forceinline__ void ldsm4(uint32_t* r, uint32_t addr) {
    asm volatile("ldmatrix.sync.aligned.m8n8.x4.shared.b16 {%0,%1,%2,%3}, [%4];"
                 : "=r"(r[0]), "=r"(r[1]), "=r"(r[2]), "=r"(r[3]) : "r"(addr));
}

__device__ __forceinline__ void ldsm4t(uint32_t* r, uint32_t addr) {
    asm volatile("ldmatrix.sync.aligned.m8n8.x4.trans.shared.b16 {%0,%1,%2,%3}, [%4];"
                 : "=r"(r[0]), "=r"(r[1]), "=r"(r[2]), "=r"(r[3]) : "r"(addr));
}

// bf16 mma
__device__ __forceinline__ void mma16816(float* c, const uint32_t* a,
                                         const uint32_t* b) {
    asm volatile(
        "mma.sync.aligned.m16n8k16.row.col.f32.bf16.bf16.f32 "
        "{%0,%1,%2,%3}, {%4,%5,%6,%7}, {%8,%9}, {%0,%1,%2,%3};"
        : "+f"(c[0]), "+f"(c[1]), "+f"(c[2]), "+f"(c[3])
        : "r"(a[0]), "r"(a[1]), "r"(a[2]), "r"(a[3]), "r"(b[0]), "r"(b[1]));
}

// fp16 mma (f32 accum)
__device__ __forceinline__ void mma16816h(float* c, const uint32_t* a,
                                          const uint32_t* b) {
    asm volatile(
        "mma.sync.aligned.m16n8k16.row.col.f32.f16.f16.f32 "
        "{%0,%1,%2,%3}, {%4,%5,%6,%7}, {%8,%9}, {%0,%1,%2,%3};"
        : "+f"(c[0]), "+f"(c[1]), "+f"(c[2]), "+f"(c[3])
        : "r"(a[0]), "r"(a[1]), "r"(a[2]), "r"(a[3]), "r"(b[0]), "r"(b[1]));
}

__device__ __forceinline__ void cpa16(uint32_t saddr, const void* g) {
    asm volatile("cp.async.cg.shared.global [%0], [%1], 16;"
                 :: "r"(saddr), "l"(g));
}
#define CP_COMMIT asm volatile("cp.async.commit_group;")
#define CP_WAIT(n) asm volatile("cp.async.wait_group %0;" :: "n"(n))

__device__ __forceinline__ float ex2(float x) {
    float r;
    asm("ex2.approx.ftz.f32 %0, %1;" : "=f"(r) : "f"(x));
    return r;
}

// fp32 -> bf16 hi/lo pair (packed as 2 elements per u32)
__device__ __forceinline__ uint32_t packsplit(float a, float b, uint32_t& lo_out) {
    __nv_bfloat16 ha = __float2bfloat16_rn(a);
    __nv_bfloat16 hb = __float2bfloat16_rn(b);
    __nv_bfloat162 hp; hp.x = ha; hp.y = hb;
    __nv_bfloat162 lp = __floats2bfloat162_rn(a - __bfloat162float(ha),
                                              b - __bfloat162float(hb));
    lo_out = reinterpret_cast<uint32_t&>(lp);
    return reinterpret_cast<uint32_t&>(hp);
}

// fp32 -> fp16 hi/lo pair
__device__ __forceinline__ uint32_t packsplit_h(float a, float b, uint32_t& lo_out) {
    __half ha = __float2half_rn(a);
    __half hb = __float2half_rn(b);
    __half2 hp = __halves2half2(ha, hb);
    __half2 lp = __floats2half2_rn(a - __half2float(ha), b - __half2float(hb));
    lo_out = reinterpret_cast<uint32_t&>(lp);
    return reinterpret_cast<uint32_t&>(hp);
}

// ---------------------------------------------------------------------------
// Conversion pre-pass (single merged launch):
//   x      -> fp16 hi/lo
//   w_qkv  -> fp16 single
//   w_proj -> bf16 hi/lo
// ---------------------------------------------------------------------------
#define X4  ((Mrows * Cdim) / 4)
#define WQ4 ((OQKV * Cdim) / 4)
#define WP4 ((Cdim * Cdim) / 4)

__global__ __launch_bounds__(256) void cvt_all(const float4* __restrict__ x,
                                               const float4* __restrict__ wq,
                                               const float4* __restrict__ wp) {
    int i = blockIdx.x * blockDim.x + threadIdx.x;
    if (i < X4) {
        float4 v = x[i];
        uint2 H, L;
        H.x = packsplit_h(v.x, v.y, L.x);
        H.y = packsplit_h(v.z, v.w, L.y);
        ((uint2*)g_xh)[i] = H;
        ((uint2*)g_xl)[i] = L;
    } else if (i < X4 + WQ4) {
        int j = i - X4;
        float4 v = wq[j];
        __half2 p0 = __floats2half2_rn(v.x, v.y);
        __half2 p1 = __floats2half2_rn(v.z, v.w);
        uint2 H;
        H.x = reinterpret_cast<uint32_t&>(p0);
        H.y = reinterpret_cast<uint32_t&>(p1);
        ((uint2*)g_wq)[j] = H;
    } else if (i < X4 + WQ4 + WP4) {
        int j = i - X4 - WQ4;
        float4 v = wp[j];
        uint2 H, L;
        H.x = packsplit(v.x, v.y, L.x);
        H.y = packsplit(v.z, v.w, L.y);
        ((uint2*)g_wphi)[j] = H;
        ((uint2*)g_wplo)[j] = L;
    }
}

// ---------------------------------------------------------------------------
// QKV GEMM, fp16 2-pass: C = (Ah + Al) * W,  A = x split fp16, W single fp16.
// CTA 128x128, 8 warps (64x32), KC=16, 4-stage cp.async, 2 CTAs/SM.
// Epilogue: scatter bf16 hi/lo into g_q/g_k/g_v (q pre-scaled).
// ---------------------------------------------------------------------------
#define KC    16
#define PITCH 48                       // 32B data + 16B pad, ldsm conflict-free
#define REGB  (128 * PITCH)            // 6144
#define QBUFB (3 * REGB)               // Ah, Al, W = 18432 per stage
#define NSTAGE 4
#define QKV_SMEM (NSTAGE * QBUFB)      // 73728

__global__ __launch_bounds__(256, 2) void qkv_f16() {
    extern __shared__ char smem[];
    const uint32_t sb = s2u(smem);
    const int tid = threadIdx.x;
    const int m0 = blockIdx.y * 128;
    const int o0 = blockIdx.x * 128;

    const __half* Ah = g_xh + (size_t)m0 * Cdim;
    const __half* Al = g_xl + (size_t)m0 * Cdim;
    const __half* Bw = g_wq + (size_t)o0 * Cdim;
    const __half* srcs[3] = {Ah, Al, Bw};

    auto issue = [&](int c, int stage) {
        uint32_t s0 = sb + stage * QBUFB;
        const int ko = c * KC;
#pragma unroll
        for (int j = 0; j < 3; j++) {
            int idx = j * 256 + tid;      // 0..767
            int mt  = idx >> 8;
            int r   = (idx >> 1) & 127;
            int c8  = idx & 1;
            cpa16(s0 + mt * REGB + r * PITCH + c8 * 16,
                  srcs[mt] + r * Cdim + ko + c8 * 8);
        }
    };

    const int wid = tid >> 5, lane = tid & 31;
    const int wm = wid >> 2;
    const int wn = wid & 3;

    const int a_row  = wm * 64 + (lane & 15);
    const int a_colb = (lane >> 4) * 16;
    const int b_row  = wn * 32 + ((lane >> 4) << 3) + (lane & 7);
    const int b_colb = ((lane >> 3) & 1) * 16;

    float acc[4][4][4];
#pragma unroll
    for (int i = 0; i < 4; i++)
#pragma unroll
        for (int j = 0; j < 4; j++)
#pragma unroll
            for (int k = 0; k < 4; k++) acc[i][j][k] = 0.0f;

    issue(0, 0); CP_COMMIT;
    issue(1, 1); CP_COMMIT;
    issue(2, 2); CP_COMMIT;

    const int NCH = Cdim / KC;   // 64
    for (int c = 0; c < NCH; c++) {
        if (c + 2 < NCH)      { CP_WAIT(2); }
        else if (c + 1 < NCH) { CP_WAIT(1); }
        else                  { CP_WAIT(0); }
        __syncthreads();

        const uint32_t base = sb + (c & 3) * QBUFB;
        uint32_t Af[4][4], Lf[4][4], Bf[2][4];
#pragma unroll
        for (int mb = 0; mb < 4; mb++) {
            uint32_t ra = base + (a_row + mb * 16) * PITCH + a_colb;
            ldsm4(Af[mb], ra);
            ldsm4(Lf[mb], ra + REGB);
        }
#pragma unroll
        for (int nbp = 0; nbp < 2; nbp++) {
            uint32_t rb = base + 2 * REGB + (b_row + nbp * 16) * PITCH + b_colb;
            ldsm4(Bf[nbp], rb);
        }
        // pass 1: Ah * W
#pragma unroll
        for (int mb = 0; mb < 4; mb++)
#pragma unroll
            for (int nb = 0; nb < 4; nb++)
                mma16816h(acc[mb][nb], Af[mb], &Bf[nb >> 1][(nb & 1) * 2]);
        // pass 2: Al * W
#pragma unroll
        for (int mb = 0; mb < 4; mb++)
#pragma unroll
            for (int nb = 0; nb < 4; nb++)
                mma16816h(acc[mb][nb], Lf[mb], &Bf[nb >> 1][(nb & 1) * 2]);

        if (c + 3 < NCH) { issue(c + 3, (c + 3) & 3); CP_COMMIT; }
    }

    const int erow = m0 + wm * 64 + (lane >> 2);
    const int ecol = o0 + wn * 32 + (lane & 3) * 2;
    const int which = o0 >> 10;
    __nv_bfloat16 *hip, *lop;
    float sc;
    const float qs = 0.125f * 1.44269504088896340736f;
    if (which == 0)      { hip = g_qhi; lop = g_qlo; sc = qs; }
    else if (which == 1) { hip = g_khi; lop = g_klo; sc = 1.0f; }
    else                 { hip = g_vhi; lop = g_vlo; sc = 1.0f; }
#pragma unroll
    for (int mb = 0; mb < 4; mb++) {
        const int m = erow + mb * 16;
        const int bb = m >> 10, n = m & 1023;
#pragma unroll
        for (int nb = 0; nb < 4; nb++) {
            const int o = ecol + nb * 8;
            const int h = (o & 1023) >> 6;
            const int d = o & 63;
            size_t base = ((size_t)(bb * Hn + h) * Nseq + n) * Dh + d;
            uint32_t L0, L1;
            uint32_t H0 = packsplit(acc[mb][nb][0] * sc, acc[mb][nb][1] * sc, L0);
            uint32_t H1 = packsplit(acc[mb][nb][2] * sc, acc[mb][nb][3] * sc, L1);
            *(uint32_t*)(hip + base)            = H0;
            *(uint32_t*)(lop + base)            = L0;
            *(uint32_t*)(hip + base + 8 * Dh)   = H1;
            *(uint32_t*)(lop + base + 8 * Dh)   = L1;
        }
    }
}

// ---------------------------------------------------------------------------
// Projection GEMM, bf16x3: out = ao * w_proj^T + bias.
// CTA 128x128, 8 warps (64x32), KC=16, 4-stage, 2 CTAs/SM.
// ---------------------------------------------------------------------------
#define PBUFB (4 * REGB)               // aohi, aolo, wphi, wplo = 24576
#define PROJ_SMEM (NSTAGE * PBUFB)     // 98304

__global__ __launch_bounds__(256, 2) void proj_bf16(const float* __restrict__ bias,
                                                    float* __restrict__ out) {
    extern __shared__ char smem[];
    const uint32_t sb = s2u(smem);
    const int tid = threadIdx.x;
    const int m0 = blockIdx.y * 128;
    const int o0 = blockIdx.x * 128;

    const __nv_bfloat16* srcs[4] = {
        g_aohi + (size_t)m0 * Cdim, g_aolo + (size_t)m0 * Cdim,
        g_wphi + (size_t)o0 * Cdim, g_wplo + (size_t)o0 * Cdim};

    auto issue = [&](int c, int stage) {
        uint32_t s0 = sb + stage * PBUFB;
        const int ko = c * KC;
#pragma unroll
        for (int j = 0; j < 4; j++) {
            int idx = j * 256 + tid;      // 0..1023
            int mt  = idx >> 8;
            int r   = (idx >> 1) & 127;
            int c8  = idx & 1;
            cpa16(s0 + mt * REGB + r * PITCH + c8 * 16,
                  srcs[mt] + r * Cdim + ko + c8 * 8);
        }
    };

    const int wid = tid >> 5, lane = tid & 31;
    const int wm = wid >> 2;
    const int wn = wid & 3;

    const int a_row  = wm * 64 + (lane & 15);
    const int a_colb = (lane >> 4) * 16;
    const int b_row  = wn * 32 + ((lane >> 4) << 3) + (lane & 7);
    const int b_colb = ((lane >> 3) & 1) * 16;

    float acc[4][4][4];
#pragma unroll
    for (int i = 0; i < 4; i++)
#pragma unroll
        for (int j = 0; j < 4; j++)
#pragma unroll
            for (int k = 0; k < 4; k++) acc[i][j][k] = 0.0f;

    issue(0, 0); CP_COMMIT;
    issue(1, 1); CP_COMMIT;
    issue(2, 2); CP_COMMIT;

    const int NCH = Cdim / KC;   // 64
    for (int c = 0; c < NCH; c++) {
        if (c + 2 < NCH)      { CP_WAIT(2); }
        else if (c + 1 < NCH) { CP_WAIT(1); }
        else                  { CP_WAIT(0); }
        __syncthreads();

        const uint32_t base = sb + (c & 3) * PBUFB;
        uint32_t Ah[4][4], Al[4][4], Bh[2][4], Bl[2][4];
#pragma unroll
        for (int mb = 0; mb < 4; mb++) {
            uint32_t ra = base + (a_row + mb * 16) * PITCH + a_colb;
            ldsm4(Ah[mb], ra);
            ldsm4(Al[mb], ra + REGB);
        }
#pragma unroll
        for (int nbp = 0; nbp < 2; nbp++) {
            uint32_t rb = base + 2 * REGB + (b_row + nbp * 16) * PITCH + b_colb;
            ldsm4(Bh[nbp], rb);
            ldsm4(Bl[nbp], rb + REGB);
        }
#pragma unroll
        for (int mb = 0; mb < 4; mb++)
#pragma unroll
            for (int nb = 0; nb < 4; nb++)
                mma16816(acc[mb][nb], Ah[mb], &Bh[nb >> 1][(nb & 1) * 2]);
#pragma unroll
        for (int mb = 0; mb < 4; mb++)
#pragma unroll
            for (int nb = 0; nb < 4; nb++)
                mma16816(acc[mb][nb], Ah[mb], &Bl[nb >> 1][(nb & 1) * 2]);
#pragma unroll
        for (int mb = 0; mb < 4; mb++)
#pragma unroll
            for (int nb = 0; nb < 4; nb++)
                mma16816(acc[mb][nb], Al[mb], &Bh[nb >> 1][(nb & 1) * 2]);

        if (c + 3 < NCH) { issue(c + 3, (c + 3) & 3); CP_COMMIT; }
    }

    const int erow = m0 + wm * 64 + (lane >> 2);
    const int ecol = o0 + wn * 32 + (lane & 3) * 2;
#pragma unroll
    for (int mb = 0; mb < 4; mb++) {
        const int m = erow + mb * 16;
#pragma unroll
        for (int nb = 0; nb < 4; nb++) {
            const int o = ecol + nb * 8;
            const float2 bv = *(const float2*)(bias + o);
            float* dst = out + (size_t)m * Cdim + o;
            *(float2*)dst = make_float2(acc[mb][nb][0] + bv.x,
                                        acc[mb][nb][1] + bv.y);
            *(float2*)(dst + 8 * Cdim) = make_float2(acc[mb][nb][2] + bv.x,
                                                     acc[mb][nb][3] + bv.y);
        }
    }
}

// ---------------------------------------------------------------------------
// Flash attention via mma.sync bf16x3 (unchanged).
// ---------------------------------------------------------------------------
#define APITCH 144
#define AQREG  (128 * APITCH)
#define AKREG  (64 * APITCH)
#define AKV0   (2 * AQREG)
#define ASTAGE (4 * AKREG)
#define ATTN_SMEM (2 * AQREG + 2 * ASTAGE)  // 110592

__global__ __launch_bounds__(256, 2) void attn_mma() {
    extern __shared__ char smem[];
    const uint32_t sb = s2u(smem);
    const int tid = threadIdx.x;
    const int w = tid >> 5, lane = tid & 31;
    const int bh = blockIdx.x;
    const int qb = blockIdx.y;

    const size_t hoff = (size_t)bh * (Nseq * Dh);
    const __nv_bfloat16* qh = g_qhi + hoff + (size_t)qb * 128 * Dh;
    const __nv_bfloat16* ql = g_qlo + hoff + (size_t)qb * 128 * Dh;

    auto loadQ = [&]() {
#pragma unroll
        for (int j = 0; j < 8; j++) {
            int idx = j * 256 + tid;
            int mt  = idx >> 10;
            int r   = (idx >> 3) & 127;
            int c8  = idx & 7;
            const __nv_bfloat16* src = mt ? ql : qh;
            cpa16(sb + mt * AQREG + r * APITCH + c8 * 16, src + r * Dh + c8 * 8);
        }
    };
    auto loadKV = [&](int kb, int st) {
        const size_t koff = hoff + (size_t)kb * 64 * Dh;
        const __nv_bfloat16* srcs[4] = {g_khi + koff, g_klo + koff,
                                        g_vhi + koff, g_vlo + koff};
        uint32_t base = sb + AKV0 + st * ASTAGE;
#pragma unroll
        for (int j = 0; j < 8; j++) {
            int idx = j * 256 + tid;
            int mt  = idx >> 9;
            int r   = (idx >> 3) & 63;
            int c8  = idx & 7;
            cpa16(base + mt * AKREG + r * APITCH + c8 * 16,
                  srcs[mt] + r * Dh + c8 * 8);
        }
    };

    loadQ();          CP_COMMIT;
    loadKV(0, 0);     CP_COMMIT;
    loadKV(1, 1);     CP_COMMIT;

    const int a_rowb = (w * 16 + (lane & 15)) * APITCH + (lane >> 4) * 16;
    const int k_rowi = ((lane >> 4) << 3) + (lane & 7);
    const int k_colb = ((lane >> 3) & 1) * 16;
    const int v_rowi = (lane & 7) + ((lane >> 3) & 1) * 8;
    const int v_colb = (lane >> 4) * 16;

    CP_WAIT(2);
    __syncthreads();

    uint32_t QAh[4][4];
#pragma unroll
    for (int kc = 0; kc < 4; kc++)
        ldsm4(QAh[kc], sb + a_rowb + kc * 32);

    float O[8][4];
#pragma unroll
    for (int i = 0; i < 8; i++)
#pragma unroll
        for (int j = 0; j < 4; j++) O[i][j] = 0.0f;
    float m0 = -1e30f, m1 = -1e30f;
    float l0 = 0.0f, l1 = 0.0f;

    for (int kb = 0; kb < 16; kb++) {
        if (kb + 1 < 16) { CP_WAIT(1); } else { CP_WAIT(0); }
        __syncthreads();
        const uint32_t kbase = sb + AKV0 + (kb & 1) * ASTAGE;

        uint32_t QAl[4][4];
#pragma unroll
        for (int kc = 0; kc < 4; kc++)
            ldsm4(QAl[kc], sb + AQREG + a_rowb + kc * 32);

        float S[8][4];
#pragma unroll
        for (int i = 0; i < 8; i++)
#pragma unroll
            for (int j = 0; j < 4; j++) S[i][j] = 0.0f;

#pragma unroll
        for (int ng = 0; ng < 4; ng++) {
#pragma unroll
            for (int kc = 0; kc < 4; kc++) {
                uint32_t kbh[4], kbl[4];
                uint32_t rb = kbase + (ng * 16 + k_rowi) * APITCH
                            + k_colb + kc * 32;
                ldsm4(kbh, rb);
                ldsm4(kbl, rb + AKREG);
#pragma unroll
                for (int half = 0; half < 2; half++) {
                    float* s = S[ng * 2 + half];
                    mma16816(s, QAh[kc], &kbh[half * 2]);
                    mma16816(s, QAh[kc], &kbl[half * 2]);
                    mma16816(s, QAl[kc], &kbh[half * 2]);
                }
            }
        }

        float rm0 = -1e30f, rm1 = -1e30f;
#pragma unroll
        for (int i = 0; i < 8; i++) {
            rm0 = fmaxf(rm0, fmaxf(S[i][0], S[i][1]));
            rm1 = fmaxf(rm1, fmaxf(S[i][2], S[i][3]));
        }
        rm0 = fmaxf(rm0, __shfl_xor_sync(0xffffffffu, rm0, 1));
        rm0 = fmaxf(rm0, __shfl_xor_sync(0xffffffffu, rm0, 2));
        rm1 = fmaxf(rm1, __shfl_xor_sync(0xffffffffu, rm1, 1));
        rm1 = fmaxf(rm1, __shfl_xor_sync(0xffffffffu, rm1, 2));

        float mn0 = fmaxf(m0, rm0), mn1 = fmaxf(m1, rm1);
        float al0 = ex2(m0 - mn0),  al1 = ex2(m1 - mn1);
        m0 = mn0; m1 = mn1;
        l0 *= al0; l1 *= al1;
#pragma unroll
        for (int i = 0; i < 8; i++) {
            O[i][0] *= al0; O[i][1] *= al0;
            O[i][2] *= al1; O[i][3] *= al1;
        }
        float ps0 = 0.0f, ps1 = 0.0f;
#pragma unroll
        for (int i = 0; i < 8; i++) {
            S[i][0] = ex2(S[i][0] - mn0);
            S[i][1] = ex2(S[i][1] - mn0);
            S[i][2] = ex2(S[i][2] - mn1);
            S[i][3] = ex2(S[i][3] - mn1);
            ps0 += S[i][0] + S[i][1];
            ps1 += S[i][2] + S[i][3];
        }
        l0 += ps0; l1 += ps1;

#pragma unroll
        for (int kc2 = 0; kc2 < 4; kc2++) {
            uint32_t pah[4], pal[4];
            pah[0] = packsplit(S[2 * kc2][0],     S[2 * kc2][1],     pal[0]);
            pah[1] = packsplit(S[2 * kc2][2],     S[2 * kc2][3],     pal[1]);
            pah[2] = packsplit(S[2 * kc2 + 1][0], S[2 * kc2 + 1][1], pal[2]);
            pah[3] = packsplit(S[2 * kc2 + 1][2], S[2 * kc2 + 1][3], pal[3]);
#pragma unroll
            for (int dg = 0; dg < 4; dg++) {
                uint32_t vbh[4], vbl[4];
                uint32_t rv = kbase + 2 * AKREG
                            + (kc2 * 16 + v_rowi) * APITCH + v_colb + dg * 32;
                ldsm4t(vbh, rv);
                ldsm4t(vbl, rv + AKREG);
#pragma unroll
                for (int half = 0; half < 2; half++) {
                    float* o = O[dg * 2 + half];
                    mma16816(o, pah, &vbh[half * 2]);
                    mma16816(o, pah, &vbl[half * 2]);
                    mma16816(o, pal, &vbh[half * 2]);
                }
            }
        }

        __syncthreads();
        if (kb + 2 < 16) { loadKV(kb + 2, kb & 1); CP_COMMIT; }
    }

    l0 += __shfl_xor_sync(0xffffffffu, l0, 1);
    l0 += __shfl_xor_sync(0xffffffffu, l0, 2);
    l1 += __shfl_xor_sync(0xffffffffu, l1, 1);
    l1 += __shfl_xor_sync(0xffffffffu, l1, 2);
    const float inv0 = 1.0f / l0, inv1 = 1.0f / l1;

    const int b = bh >> 4, h = bh & 15;
    const int n0 = qb * 128 + w * 16 + (lane >> 2);
#pragma unroll
    for (int nb = 0; nb < 8; nb++) {
        const int d = nb * 8 + (lane & 3) * 2;
        size_t base0 = ((size_t)(b * Nseq + n0) * Cdim) + h * Dh + d;
        size_t base1 = base0 + (size_t)8 * Cdim;
        uint32_t L0, L1;
        uint32_t H0 = packsplit(O[nb][0] * inv0, O[nb][1] * inv0, L0);
        uint32_t H1 = packsplit(O[nb][2] * inv1, O[nb][3] * inv1, L1);
        *(uint32_t*)(g_aohi + base0) = H0;
        *(uint32_t*)(g_aolo + base0) = L0;
        *(uint32_t*)(g_aohi + base1) = H1;
        *(uint32_t*)(g_aolo + base1) = L1;
    }
}

// ---------------------------------------------------------------------------
extern "C" void kernel_launch(void* const* d_in, const int* in_sizes, int n_in,
                              void* d_out, int out_size) {
    const float* x      = (const float*)d_in[0];   // [8,1024,1024]
    const float* w_qkv  = (const float*)d_in[1];   // [3072,1024]
    const float* w_proj = (const float*)d_in[2];   // [1024,1024]
    const float* b_proj = (const float*)d_in[3];   // [1024]
    float* out = (float*)d_out;

    cudaFuncSetAttribute(qkv_f16,
                         cudaFuncAttributeMaxDynamicSharedMemorySize, QKV_SMEM);
    cudaFuncSetAttribute(proj_bf16,
                         cudaFuncAttributeMaxDynamicSharedMemorySize, PROJ_SMEM);
    cudaFuncSetAttribute(attn_mma,
                         cudaFuncAttributeMaxDynamicSharedMemorySize, ATTN_SMEM);

    {
        int n4 = X4 + WQ4 + WP4;
        cvt_all<<<(n4 + 255) / 256, 256>>>((const float4*)x,
                                           (const float4*)w_qkv,
                                           (const float4*)w_proj);
    }

    dim3 g1(OQKV / 128, Mrows / 128);              // (24, 64)
    qkv_f16<<<g1, 256, QKV_SMEM>>>();

    dim3 g2(Bsz * Hn, Nseq / 128);                 // (128, 8)
    attn_mma<<<g2, 256, ATTN_SMEM>>>();

    dim3 g3(Cdim / 128, Mrows / 128);              // (8, 64)
    proj_bf16<<<g3, 256, PROJ_SMEM>>>(b_proj, out);
}

// round 11
// speedup vs baseline: 1.5884x; 1.2849x over previous
#include <cuda_runtime.h>
#include <cuda_bf16.h>
#include <cuda_fp16.h>
#include <math_constants.h>
#include <cstdint>

#define Bsz  8
#define Nseq 1024
#define Cdim 1024
#define Hn   16
#define Dh   64
#define Mrows (Bsz * Nseq)
#define OQKV 3072

// ---------------------------------------------------------------------------
// Device-global scratch (allocation-free rule)
// ---------------------------------------------------------------------------
__device__ __half g_xh[Mrows * Cdim];          // x fp16 hi
__device__ __half g_xl[Mrows * Cdim];          // x fp16 lo
__device__ __half g_wq[OQKV * Cdim];           // w_qkv fp16 single
__device__ __half g_wp[Cdim * Cdim];           // w_proj fp16 single
__device__ __half g_aoh[Mrows * Cdim];         // attention out fp16 hi/lo
__device__ __half g_aol[Mrows * Cdim];

// Q split fp16 (pre-scaled), K/V single fp16; layout [b*H+h][n][d]
__device__ __half g_qh[Bsz * Hn * Nseq * Dh];
__device__ __half g_ql[Bsz * Hn * Nseq * Dh];
__device__ __half g_k [Bsz * Hn * Nseq * Dh];
__device__ __half g_v [Bsz * Hn * Nseq * Dh];

// ---------------------------------------------------------------------------
// PTX helpers (base ISA: ldmatrix / mma.sync / cp.async)
// ---------------------------------------------------------------------------
__device__ __forceinline__ uint32_t s2u(const void* p) {
    uint32_t a;
    asm("{ .reg .u64 t; cvta.to.shared.u64 t, %1; cvt.u32.u64 %0, t; }"
        : "=r"(a) : "l"(p));
    return a;
}

__device__ __forceinline__ void ldsm4(uint32_t* r, uint32_t addr) {
    asm volatile("ldmatrix.sync.aligned.m8n8.x4.shared.b16 {%0,%1,%2,%3}, [%4];"
                 : "=r"(r[0]), "=r"(r[1]), "=r"(r[2]), "=r"(r[3]) : "r"(addr));
}

__device__ __forceinline__ void ldsm4t(uint32_t* r, uint32_t addr) {
    asm volatile("ldmatrix.sync.aligned.m8n8.x4.trans.shared.b16 {%0,%1,%2,%3}, [%4];"
                 : "=r"(r[0]), "=r"(r[1]), "=r"(r[2]), "=r"(r[3]) : "r"(addr));
}

// fp16 mma (f32 accum)
__device__ __forceinline__ void mma16816h(float* c, const uint32_t* a,
                                          const uint32_t* b) {
    asm volatile(
        "mma.sync.aligned.m16n8k16.row.col.f32.f16.f16.f32 "
        "{%0,%1,%2,%3}, {%4,%5,%6,%7}, {%8,%9}, {%0,%1,%2,%3};"
        : "+f"(c[0]), "+f"(c[1]), "+f"(c[2]), "+f"(c[3])
        : "r"(a[0]), "r"(a[1]), "r"(a[2]), "r"(a[3]), "r"(b[0]), "r"(b[1]));
}

__device__ __forceinline__ void cpa16(uint32_t saddr, const void* g) {
    asm volatile("cp.async.cg.shared.global [%0], [%1], 16;"
                 :: "r"(saddr), "l"(g));
}
#define CP_COMMIT asm volatile("cp.async.commit_group;")
#define CP_WAIT(n) asm volatile("cp.async.wait_group %0;" :: "n"(n))

__device__ __forceinline__ float ex2(float x) {
    float r;
    asm("ex2.approx.ftz.f32 %0, %1;" : "=f"(r) : "f"(x));
    return r;
}

// fp32 -> fp16 hi/lo pair
__device__ __forceinline__ uint32_t packsplit_h(float a, float b, uint32_t& lo_out) {
    __half ha = __float2half_rn(a);
    __half hb = __float2half_rn(b);
    __half2 hp = __halves2half2(ha, hb);
    __half2 lp = __floats2half2_rn(a - __half2float(ha), b - __half2float(hb));
    lo_out = reinterpret_cast<uint32_t&>(lp);
    return reinterpret_cast<uint32_t&>(hp);
}

// fp32 pair -> packed fp16x2
__device__ __forceinline__ uint32_t packh2(float a, float b) {
    __half2 p = __floats2half2_rn(a, b);
    return reinterpret_cast<uint32_t&>(p);
}

// ---------------------------------------------------------------------------
// Conversion pre-pass (single merged launch):
//   x -> fp16 hi/lo;  w_qkv -> fp16 single;  w_proj -> fp16 single
// ---------------------------------------------------------------------------
#define X4  ((Mrows * Cdim) / 4)
#define WQ4 ((OQKV * Cdim) / 4)
#define WP4 ((Cdim * Cdim) / 4)

__global__ __launch_bounds__(256) void cvt_all(const float4* __restrict__ x,
                                               const float4* __restrict__ wq,
                                               const float4* __restrict__ wp) {
    int i = blockIdx.x * blockDim.x + threadIdx.x;
    if (i < X4) {
        float4 v = x[i];
        uint2 H, L;
        H.x = packsplit_h(v.x, v.y, L.x);
        H.y = packsplit_h(v.z, v.w, L.y);
        ((uint2*)g_xh)[i] = H;
        ((uint2*)g_xl)[i] = L;
    } else if (i < X4 + WQ4) {
        int j = i - X4;
        float4 v = wq[j];
        uint2 H;
        H.x = packh2(v.x, v.y);
        H.y = packh2(v.z, v.w);
        ((uint2*)g_wq)[j] = H;
    } else if (i < X4 + WQ4 + WP4) {
        int j = i - X4 - WQ4;
        float4 v = wp[j];
        uint2 H;
        H.x = packh2(v.x, v.y);
        H.y = packh2(v.z, v.w);
        ((uint2*)g_wp)[j] = H;
    }
}

// ---------------------------------------------------------------------------
// fp16 2-pass GEMM core config (shared by qkv_f16 / proj_f16):
// CTA 128x128, 8 warps (64x32), KC=16, 4-stage cp.async, 2 CTAs/SM.
// ---------------------------------------------------------------------------
#define KC    16
#define PITCH 48                       // 32B data + 16B pad, ldsm conflict-free
#define REGB  (128 * PITCH)            // 6144
#define GBUFB (3 * REGB)               // Ah, Al, W = 18432 per stage
#define NSTAGE 4
#define GEMM_SMEM (NSTAGE * GBUFB)     // 73728

// ---------------------------------------------------------------------------
// QKV GEMM: C = (xh + xl) * wq.  Epilogue: q split fp16 (pre-scaled),
// k single fp16, v single fp16, layout [b*H+h][n][d].
// ---------------------------------------------------------------------------
__global__ __launch_bounds__(256, 2) void qkv_f16() {
    extern __shared__ char smem[];
    const uint32_t sb = s2u(smem);
    const int tid = threadIdx.x;
    const int m0 = blockIdx.y * 128;
    const int o0 = blockIdx.x * 128;

    const __half* srcs[3] = {g_xh + (size_t)m0 * Cdim,
                             g_xl + (size_t)m0 * Cdim,
                             g_wq + (size_t)o0 * Cdim};

    auto issue = [&](int c, int stage) {
        uint32_t s0 = sb + stage * GBUFB;
        const int ko = c * KC;
#pragma unroll
        for (int j = 0; j < 3; j++) {
            int idx = j * 256 + tid;
            int mt  = idx >> 8;
            int r   = (idx >> 1) & 127;
            int c8  = idx & 1;
            cpa16(s0 + mt * REGB + r * PITCH + c8 * 16,
                  srcs[mt] + r * Cdim + ko + c8 * 8);
        }
    };

    const int wid = tid >> 5, lane = tid & 31;
    const int wm = wid >> 2;
    const int wn = wid & 3;

    const int a_row  = wm * 64 + (lane & 15);
    const int a_colb = (lane >> 4) * 16;
    const int b_row  = wn * 32 + ((lane >> 4) << 3) + (lane & 7);
    const int b_colb = ((lane >> 3) & 1) * 16;

    float acc[4][4][4];
#pragma unroll
    for (int i = 0; i < 4; i++)
#pragma unroll
        for (int j = 0; j < 4; j++)
#pragma unroll
            for (int k = 0; k < 4; k++) acc[i][j][k] = 0.0f;

    issue(0, 0); CP_COMMIT;
    issue(1, 1); CP_COMMIT;
    issue(2, 2); CP_COMMIT;

    const int NCH = Cdim / KC;
    for (int c = 0; c < NCH; c++) {
        if (c + 2 < NCH)      { CP_WAIT(2); }
        else if (c + 1 < NCH) { CP_WAIT(1); }
        else                  { CP_WAIT(0); }
        __syncthreads();

        const uint32_t base = sb + (c & 3) * GBUFB;
        uint32_t Af[4][4], Lf[4][4], Bf[2][4];
#pragma unroll
        for (int mb = 0; mb < 4; mb++) {
            uint32_t ra = base + (a_row + mb * 16) * PITCH + a_colb;
            ldsm4(Af[mb], ra);
            ldsm4(Lf[mb], ra + REGB);
        }
#pragma unroll
        for (int nbp = 0; nbp < 2; nbp++) {
            uint32_t rb = base + 2 * REGB + (b_row + nbp * 16) * PITCH + b_colb;
            ldsm4(Bf[nbp], rb);
        }
#pragma unroll
        for (int mb = 0; mb < 4; mb++)
#pragma unroll
            for (int nb = 0; nb < 4; nb++)
                mma16816h(acc[mb][nb], Af[mb], &Bf[nb >> 1][(nb & 1) * 2]);
#pragma unroll
        for (int mb = 0; mb < 4; mb++)
#pragma unroll
            for (int nb = 0; nb < 4; nb++)
                mma16816h(acc[mb][nb], Lf[mb], &Bf[nb >> 1][(nb & 1) * 2]);

        if (c + 3 < NCH) { issue(c + 3, (c + 3) & 3); CP_COMMIT; }
    }

    const int erow = m0 + wm * 64 + (lane >> 2);
    const int ecol = o0 + wn * 32 + (lane & 3) * 2;
    const int which = o0 >> 10;     // 0=q 1=k 2=v
    const float qs = 0.125f * 1.44269504088896340736f;
#pragma unroll
    for (int mb = 0; mb < 4; mb++) {
        const int m = erow + mb * 16;
        const int bb = m >> 10, n = m & 1023;
#pragma unroll
        for (int nb = 0; nb < 4; nb++) {
            const int o = ecol + nb * 8;
            const int h = (o & 1023) >> 6;
            const int d = o & 63;
            size_t base = ((size_t)(bb * Hn + h) * Nseq + n) * Dh + d;
            if (which == 0) {
                uint32_t L0, L1;
                uint32_t H0 = packsplit_h(acc[mb][nb][0] * qs, acc[mb][nb][1] * qs, L0);
                uint32_t H1 = packsplit_h(acc[mb][nb][2] * qs, acc[mb][nb][3] * qs, L1);
                *(uint32_t*)(g_qh + base)          = H0;
                *(uint32_t*)(g_ql + base)          = L0;
                *(uint32_t*)(g_qh + base + 8 * Dh) = H1;
                *(uint32_t*)(g_ql + base + 8 * Dh) = L1;
            } else {
                __half* dst = (which == 1) ? g_k : g_v;
                *(uint32_t*)(dst + base)          = packh2(acc[mb][nb][0], acc[mb][nb][1]);
                *(uint32_t*)(dst + base + 8 * Dh) = packh2(acc[mb][nb][2], acc[mb][nb][3]);
            }
        }
    }
}

// ---------------------------------------------------------------------------
// Projection GEMM: out = (aoh + aol) * wp^T + bias.  fp16 2-pass.
// ---------------------------------------------------------------------------
__global__ __launch_bounds__(256, 2) void proj_f16(const float* __restrict__ bias,
                                                   float* __restrict__ out) {
    extern __shared__ char smem[];
    const uint32_t sb = s2u(smem);
    const int tid = threadIdx.x;
    const int m0 = blockIdx.y * 128;
    const int o0 = blockIdx.x * 128;

    const __half* srcs[3] = {g_aoh + (size_t)m0 * Cdim,
                             g_aol + (size_t)m0 * Cdim,
                             g_wp  + (size_t)o0 * Cdim};

    auto issue = [&](int c, int stage) {
        uint32_t s0 = sb + stage * GBUFB;
        const int ko = c * KC;
#pragma unroll
        for (int j = 0; j < 3; j++) {
            int idx = j * 256 + tid;
            int mt  = idx >> 8;
            int r   = (idx >> 1) & 127;
            int c8  = idx & 1;
            cpa16(s0 + mt * REGB + r * PITCH + c8 * 16,
                  srcs[mt] + r * Cdim + ko + c8 * 8);
        }
    };

    const int wid = tid >> 5, lane = tid & 31;
    const int wm = wid >> 2;
    const int wn = wid & 3;

    const int a_row  = wm * 64 + (lane & 15);
    const int a_colb = (lane >> 4) * 16;
    const int b_row  = wn * 32 + ((lane >> 4) << 3) + (lane & 7);
    const int b_colb = ((lane >> 3) & 1) * 16;

    float acc[4][4][4];
#pragma unroll
    for (int i = 0; i < 4; i++)
#pragma unroll
        for (int j = 0; j < 4; j++)
#pragma unroll
            for (int k = 0; k < 4; k++) acc[i][j][k] = 0.0f;

    issue(0, 0); CP_COMMIT;
    issue(1, 1); CP_COMMIT;
    issue(2, 2); CP_COMMIT;

    const int NCH = Cdim / KC;
    for (int c = 0; c < NCH; c++) {
        if (c + 2 < NCH)      { CP_WAIT(2); }
        else if (c + 1 < NCH) { CP_WAIT(1); }
        else                  { CP_WAIT(0); }
        __syncthreads();

        const uint32_t base = sb + (c & 3) * GBUFB;
        uint32_t Af[4][4], Lf[4][4], Bf[2][4];
#pragma unroll
        for (int mb = 0; mb < 4; mb++) {
            uint32_t ra = base + (a_row + mb * 16) * PITCH + a_colb;
            ldsm4(Af[mb], ra);
            ldsm4(Lf[mb], ra + REGB);
        }
#pragma unroll
        for (int nbp = 0; nbp < 2; nbp++) {
            uint32_t rb = base + 2 * REGB + (b_row + nbp * 16) * PITCH + b_colb;
            ldsm4(Bf[nbp], rb);
        }
#pragma unroll
        for (int mb = 0; mb < 4; mb++)
#pragma unroll
            for (int nb = 0; nb < 4; nb++)
                mma16816h(acc[mb][nb], Af[mb], &Bf[nb >> 1][(nb & 1) * 2]);
#pragma unroll
        for (int mb = 0; mb < 4; mb++)
#pragma unroll
            for (int nb = 0; nb < 4; nb++)
                mma16816h(acc[mb][nb], Lf[mb], &Bf[nb >> 1][(nb & 1) * 2]);

        if (c + 3 < NCH) { issue(c + 3, (c + 3) & 3); CP_COMMIT; }
    }

    const int erow = m0 + wm * 64 + (lane >> 2);
    const int ecol = o0 + wn * 32 + (lane & 3) * 2;
#pragma unroll
    for (int mb = 0; mb < 4; mb++) {
        const int m = erow + mb * 16;
#pragma unroll
        for (int nb = 0; nb < 4; nb++) {
            const int o = ecol + nb * 8;
            const float2 bv = *(const float2*)(bias + o);
            float* dst = out + (size_t)m * Cdim + o;
            *(float2*)dst = make_float2(acc[mb][nb][0] + bv.x,
                                        acc[mb][nb][1] + bv.y);
            *(float2*)(dst + 8 * Cdim) = make_float2(acc[mb][nb][2] + bv.x,
                                                     acc[mb][nb][3] + bv.y);
        }
    }
}

// ---------------------------------------------------------------------------
// Flash attention, fp16:
//   S = (Qh + Ql) * K^T   (2 passes, K single fp16)
//   O += P * V            (1 pass; P packed single fp16, V single fp16)
// CTA: 128 Q rows x one (b,h), 8 warps, KV in 64-row tiles, 2-stage cp.async.
// Epilogue: ao split fp16 hi/lo for proj.
// ---------------------------------------------------------------------------
#define APITCH 144
#define AQREG  (128 * APITCH)            // 18432 per Q matrix
#define AKREG  (64 * APITCH)             // 9216 per KV matrix
#define AKV0   (2 * AQREG)               // 36864
#define ASTAGE (2 * AKREG)               // K, V = 18432
#define ATTN_SMEM (2 * AQREG + 2 * ASTAGE)  // 73728

__global__ __launch_bounds__(256, 2) void attn_f16() {
    extern __shared__ char smem[];
    const uint32_t sb = s2u(smem);
    const int tid = threadIdx.x;
    const int w = tid >> 5, lane = tid & 31;
    const int bh = blockIdx.x;
    const int qb = blockIdx.y;

    const size_t hoff = (size_t)bh * (Nseq * Dh);
    const __half* qh = g_qh + hoff + (size_t)qb * 128 * Dh;
    const __half* ql = g_ql + hoff + (size_t)qb * 128 * Dh;

    auto loadQ = [&]() {
#pragma unroll
        for (int j = 0; j < 8; j++) {
            int idx = j * 256 + tid;          // 0..2047
            int mt  = idx >> 10;
            int r   = (idx >> 3) & 127;
            int c8  = idx & 7;
            const __half* src = mt ? ql : qh;
            cpa16(sb + mt * AQREG + r * APITCH + c8 * 16, src + r * Dh + c8 * 8);
        }
    };
    auto loadKV = [&](int kb, int st) {     // kb: 64-row block 0..15
        const size_t koff = hoff + (size_t)kb * 64 * Dh;
        const __half* srcs[2] = {g_k + koff, g_v + koff};
        uint32_t base = sb + AKV0 + st * ASTAGE;
#pragma unroll
        for (int j = 0; j < 4; j++) {
            int idx = j * 256 + tid;          // 0..1023
            int mt  = idx >> 9;               // 0=K 1=V
            int r   = (idx >> 3) & 63;
            int c8  = idx & 7;
            cpa16(base + mt * AKREG + r * APITCH + c8 * 16,
                  srcs[mt] + r * Dh + c8 * 8);
        }
    };

    loadQ();          CP_COMMIT;
    loadKV(0, 0);     CP_COMMIT;
    loadKV(1, 1);     CP_COMMIT;

    const int a_rowb = (w * 16 + (lane & 15)) * APITCH + (lane >> 4) * 16;
    const int k_rowi = ((lane >> 4) << 3) + (lane & 7);
    const int k_colb = ((lane >> 3) & 1) * 16;
    const int v_rowi = (lane & 7) + ((lane >> 3) & 1) * 8;
    const int v_colb = (lane >> 4) * 16;

    CP_WAIT(2);
    __syncthreads();

    uint32_t QAh[4][4], QAl[4][4];
#pragma unroll
    for (int kc = 0; kc < 4; kc++) {
        ldsm4(QAh[kc], sb + a_rowb + kc * 32);
        ldsm4(QAl[kc], sb + AQREG + a_rowb + kc * 32);
    }

    float O[8][4];
#pragma unroll
    for (int i = 0; i < 8; i++)
#pragma unroll
        for (int j = 0; j < 4; j++) O[i][j] = 0.0f;
    float m0 = -1e30f, m1 = -1e30f;
    float l0 = 0.0f, l1 = 0.0f;

    for (int kb = 0; kb < 16; kb++) {
        if (kb + 1 < 16) { CP_WAIT(1); } else { CP_WAIT(0); }
        __syncthreads();
        const uint32_t kbase = sb + AKV0 + (kb & 1) * ASTAGE;

        // ----- S = Q K^T (2 passes), 64 cols = 4 n-groups ------------------
        float S[8][4];
#pragma unroll
        for (int i = 0; i < 8; i++)
#pragma unroll
            for (int j = 0; j < 4; j++) S[i][j] = 0.0f;

#pragma unroll
        for (int ng = 0; ng < 4; ng++) {
#pragma unroll
            for (int kc = 0; kc < 4; kc++) {
                uint32_t kf[4];
                ldsm4(kf, kbase + (ng * 16 + k_rowi) * APITCH + k_colb + kc * 32);
#pragma unroll
                for (int half = 0; half < 2; half++) {
                    float* s = S[ng * 2 + half];
                    mma16816h(s, QAh[kc], &kf[half * 2]);
                    mma16816h(s, QAl[kc], &kf[half * 2]);
                }
            }
        }

        // ----- online softmax ---------------------------------------------
        float rm0 = -1e30f, rm1 = -1e30f;
#pragma unroll
        for (int i = 0; i < 8; i++) {
            rm0 = fmaxf(rm0, fmaxf(S[i][0], S[i][1]));
            rm1 = fmaxf(rm1, fmaxf(S[i][2], S[i][3]));
        }
        rm0 = fmaxf(rm0, __shfl_xor_sync(0xffffffffu, rm0, 1));
        rm0 = fmaxf(rm0, __shfl_xor_sync(0xffffffffu, rm0, 2));
        rm1 = fmaxf(rm1, __shfl_xor_sync(0xffffffffu, rm1, 1));
        rm1 = fmaxf(rm1, __shfl_xor_sync(0xffffffffu, rm1, 2));

        float mn0 = fmaxf(m0, rm0), mn1 = fmaxf(m1, rm1);
        float al0 = ex2(m0 - mn0),  al1 = ex2(m1 - mn1);
        m0 = mn0; m1 = mn1;
        l0 *= al0; l1 *= al1;
#pragma unroll
        for (int i = 0; i < 8; i++) {
            O[i][0] *= al0; O[i][1] *= al0;
            O[i][2] *= al1; O[i][3] *= al1;
        }
        float ps0 = 0.0f, ps1 = 0.0f;
#pragma unroll
        for (int i = 0; i < 8; i++) {
            S[i][0] = ex2(S[i][0] - mn0);
            S[i][1] = ex2(S[i][1] - mn0);
            S[i][2] = ex2(S[i][2] - mn1);
            S[i][3] = ex2(S[i][3] - mn1);
            ps0 += S[i][0] + S[i][1];
            ps1 += S[i][2] + S[i][3];
        }
        l0 += ps0; l1 += ps1;

        // ----- O += P V (1 pass; P single fp16) ----------------------------
#pragma unroll
        for (int kc2 = 0; kc2 < 4; kc2++) {
            uint32_t pf[4];
            pf[0] = packh2(S[2 * kc2][0],     S[2 * kc2][1]);
            pf[1] = packh2(S[2 * kc2][2],     S[2 * kc2][3]);
            pf[2] = packh2(S[2 * kc2 + 1][0], S[2 * kc2 + 1][1]);
            pf[3] = packh2(S[2 * kc2 + 1][2], S[2 * kc2 + 1][3]);
#pragma unroll
            for (int dg = 0; dg < 4; dg++) {
                uint32_t vf[4];
                ldsm4t(vf, kbase + AKREG
                           + (kc2 * 16 + v_rowi) * APITCH + v_colb + dg * 32);
#pragma unroll
                for (int half = 0; half < 2; half++)
                    mma16816h(O[dg * 2 + half], pf, &vf[half * 2]);
            }
        }

        __syncthreads();
        if (kb + 2 < 16) { loadKV(kb + 2, kb & 1); CP_COMMIT; }
    }

    // ----- finalize + write fp16 hi/lo ao for proj -------------------------
    l0 += __shfl_xor_sync(0xffffffffu, l0, 1);
    l0 += __shfl_xor_sync(0xffffffffu, l0, 2);
    l1 += __shfl_xor_sync(0xffffffffu, l1, 1);
    l1 += __shfl_xor_sync(0xffffffffu, l1, 2);
    const float inv0 = 1.0f / l0, inv1 = 1.0f / l1;

    const int b = bh >> 4, h = bh & 15;
    const int n0 = qb * 128 + w * 16 + (lane >> 2);
#pragma unroll
    for (int nb = 0; nb < 8; nb++) {
        const int d = nb * 8 + (lane & 3) * 2;
        size_t base0 = ((size_t)(b * Nseq + n0) * Cdim) + h * Dh + d;
        size_t base1 = base0 + (size_t)8 * Cdim;
        uint32_t L0, L1;
        uint32_t H0 = packsplit_h(O[nb][0] * inv0, O[nb][1] * inv0, L0);
        uint32_t H1 = packsplit_h(O[nb][2] * inv1, O[nb][3] * inv1, L1);
        *(uint32_t*)(g_aoh + base0) = H0;
        *(uint32_t*)(g_aol + base0) = L0;
        *(uint32_t*)(g_aoh + base1) = H1;
        *(uint32_t*)(g_aol + base1) = L1;
    }
}

// ---------------------------------------------------------------------------
extern "C" void kernel_launch(void* const* d_in, const int* in_sizes, int n_in,
                              void* d_out, int out_size) {
    const float* x      = (const float*)d_in[0];   // [8,1024,1024]
    const float* w_qkv  = (const float*)d_in[1];   // [3072,1024]
    const float* w_proj = (const float*)d_in[2];   // [1024,1024]
    const float* b_proj = (const float*)d_in[3];   // [1024]
    float* out = (float*)d_out;

    cudaFuncSetAttribute(qkv_f16,
                         cudaFuncAttributeMaxDynamicSharedMemorySize, GEMM_SMEM);
    cudaFuncSetAttribute(proj_f16,
                         cudaFuncAttributeMaxDynamicSharedMemorySize, GEMM_SMEM);
    cudaFuncSetAttribute(attn_f16,
                         cudaFuncAttributeMaxDynamicSharedMemorySize, ATTN_SMEM);

    {
        int n4 = X4 + WQ4 + WP4;
        cvt_all<<<(n4 + 255) / 256, 256>>>((const float4*)x,
                                           (const float4*)w_qkv,
                                           (const float4*)w_proj);
    }

    dim3 g1(OQKV / 128, Mrows / 128);              // (24, 64)
    qkv_f16<<<g1, 256, GEMM_SMEM>>>();

    dim3 g2(Bsz * Hn, Nseq / 128);                 // (128, 8)
    attn_f16<<<g2, 256, ATTN_SMEM>>>();

    dim3 g3(Cdim / 128, Mrows / 128);              // (8, 64)
    proj_f16<<<g3, 256, GEMM_SMEM>>>(b_proj, out);
}

// round 12
// speedup vs baseline: 1.7733x; 1.1164x over previous
#include <cuda_runtime.h>
#include <cuda_fp16.h>
#include <math_constants.h>
#include <cstdint>

#define Bsz  8
#define Nseq 1024
#define Cdim 1024
#define Hn   16
#define Dh   64
#define Mrows (Bsz * Nseq)
#define OQKV 3072

// ---------------------------------------------------------------------------
// Device-global scratch (allocation-free rule) — all single fp16
// ---------------------------------------------------------------------------
__device__ __half g_x16[Mrows * Cdim];         // x
__device__ __half g_wq [OQKV * Cdim];          // w_qkv
__device__ __half g_wp [Cdim * Cdim];          // w_proj
__device__ __half g_ao [Mrows * Cdim];         // attention out
__device__ __half g_q  [Bsz * Hn * Nseq * Dh]; // q (pre-scaled)
__device__ __half g_k  [Bsz * Hn * Nseq * Dh];
__device__ __half g_v  [Bsz * Hn * Nseq * Dh];

// ---------------------------------------------------------------------------
// PTX helpers
// ---------------------------------------------------------------------------
__device__ __forceinline__ uint32_t s2u(const void* p) {
    uint32_t a;
    asm("{ .reg .u64 t; cvta.to.shared.u64 t, %1; cvt.u32.u64 %0, t; }"
        : "=r"(a) : "l"(p));
    return a;
}

__device__ __forceinline__ void ldsm4(uint32_t* r, uint32_t addr) {
    asm volatile("ldmatrix.sync.aligned.m8n8.x4.shared.b16 {%0,%1,%2,%3}, [%4];"
                 : "=r"(r[0]), "=r"(r[1]), "=r"(r[2]), "=r"(r[3]) : "r"(addr));
}

__device__ __forceinline__ void ldsm4t(uint32_t* r, uint32_t addr) {
    asm volatile("ldmatrix.sync.aligned.m8n8.x4.trans.shared.b16 {%0,%1,%2,%3}, [%4];"
                 : "=r"(r[0]), "=r"(r[1]), "=r"(r[2]), "=r"(r[3]) : "r"(addr));
}

__device__ __forceinline__ void mma16816h(float* c, const uint32_t* a,
                                          const uint32_t* b) {
    asm volatile(
        "mma.sync.aligned.m16n8k16.row.col.f32.f16.f16.f32 "
        "{%0,%1,%2,%3}, {%4,%5,%6,%7}, {%8,%9}, {%0,%1,%2,%3};"
        : "+f"(c[0]), "+f"(c[1]), "+f"(c[2]), "+f"(c[3])
        : "r"(a[0]), "r"(a[1]), "r"(a[2]), "r"(a[3]), "r"(b[0]), "r"(b[1]));
}

__device__ __forceinline__ void cpa16(uint32_t saddr, const void* g) {
    asm volatile("cp.async.cg.shared.global [%0], [%1], 16;"
                 :: "r"(saddr), "l"(g));
}
#define CP_COMMIT asm volatile("cp.async.commit_group;")
#define CP_WAIT(n) asm volatile("cp.async.wait_group %0;" :: "n"(n))

__device__ __forceinline__ float ex2(float x) {
    float r;
    asm("ex2.approx.ftz.f32 %0, %1;" : "=f"(r) : "f"(x));
    return r;
}

__device__ __forceinline__ uint32_t packh2(float a, float b) {
    __half2 p = __floats2half2_rn(a, b);
    return reinterpret_cast<uint32_t&>(p);
}

// ---------------------------------------------------------------------------
// Conversion pre-pass: everything -> single fp16 (one merged launch)
// ---------------------------------------------------------------------------
#define X4  ((Mrows * Cdim) / 4)
#define WQ4 ((OQKV * Cdim) / 4)
#define WP4 ((Cdim * Cdim) / 4)

__global__ __launch_bounds__(256) void cvt_all(const float4* __restrict__ x,
                                               const float4* __restrict__ wq,
                                               const float4* __restrict__ wp) {
    int i = blockIdx.x * blockDim.x + threadIdx.x;
    const float4* in;
    __half* dst;
    int j;
    if (i < X4)                { in = x;  dst = g_x16; j = i; }
    else if (i < X4 + WQ4)     { in = wq; dst = g_wq;  j = i - X4; }
    else if (i < X4 + WQ4 + WP4) { in = wp; dst = g_wp; j = i - X4 - WQ4; }
    else return;
    float4 v = in[j];
    uint2 H;
    H.x = packh2(v.x, v.y);
    H.y = packh2(v.z, v.w);
    ((uint2*)dst)[j] = H;
}

// ---------------------------------------------------------------------------
// fp16 single-pass GEMM: C[m,o] = sum_k A[m,k] * B[o,k]
// CTA 128x128, 8 warps (64x32), KC=32, 4-stage cp.async, 2 CTAs/SM.
// mode 0: scatter q/k/v fp16 (q pre-scaled);  mode 1: +bias -> fp32 out.
// ---------------------------------------------------------------------------
#define KC    32
#define PITCH 80                       // 64B data + 16B pad, ldsm conflict-free
#define REGB  (128 * PITCH)            // 10240
#define GBUFB (2 * REGB)               // A, B = 20480 per stage
#define NSTAGE 4
#define GEMM_SMEM (NSTAGE * GBUFB)     // 81920

__global__ __launch_bounds__(256, 2) void gemm_f16(int mode,
                                                   const float* __restrict__ bias,
                                                   float* __restrict__ out) {
    extern __shared__ char smem[];
    const uint32_t sb = s2u(smem);
    const int tid = threadIdx.x;
    const int m0 = blockIdx.y * 128;
    const int o0 = blockIdx.x * 128;

    const __half* srcs[2] = {
        ((mode == 0) ? g_x16 : g_ao) + (size_t)m0 * Cdim,
        ((mode == 0) ? g_wq  : g_wp) + (size_t)o0 * Cdim};

    auto issue = [&](int c, int stage) {
        uint32_t s0 = sb + stage * GBUFB;
        const int ko = c * KC;
#pragma unroll
        for (int j = 0; j < 4; j++) {
            int idx = j * 256 + tid;      // 0..1023
            int mt  = idx >> 9;
            int r   = (idx >> 2) & 127;
            int c8  = idx & 3;
            cpa16(s0 + mt * REGB + r * PITCH + c8 * 16,
                  srcs[mt] + r * Cdim + ko + c8 * 8);
        }
    };

    const int wid = tid >> 5, lane = tid & 31;
    const int wm = wid >> 2;
    const int wn = wid & 3;

    const int a_row  = wm * 64 + (lane & 15);
    const int a_colb = (lane >> 4) * 16;
    const int b_row  = wn * 32 + ((lane >> 4) << 3) + (lane & 7);
    const int b_colb = ((lane >> 3) & 1) * 16;

    float acc[4][4][4];
#pragma unroll
    for (int i = 0; i < 4; i++)
#pragma unroll
        for (int j = 0; j < 4; j++)
#pragma unroll
            for (int k = 0; k < 4; k++) acc[i][j][k] = 0.0f;

    issue(0, 0); CP_COMMIT;
    issue(1, 1); CP_COMMIT;
    issue(2, 2); CP_COMMIT;

    const int NCH = Cdim / KC;   // 32
    for (int c = 0; c < NCH; c++) {
        if (c + 2 < NCH)      { CP_WAIT(2); }
        else if (c + 1 < NCH) { CP_WAIT(1); }
        else                  { CP_WAIT(0); }
        __syncthreads();

        const uint32_t base = sb + (c & 3) * GBUFB;
#pragma unroll
        for (int ks = 0; ks < 2; ks++) {
            uint32_t Af[4][4], Bf[2][4];
#pragma unroll
            for (int mb = 0; mb < 4; mb++)
                ldsm4(Af[mb], base + (a_row + mb * 16) * PITCH + ks * 32 + a_colb);
#pragma unroll
            for (int nbp = 0; nbp < 2; nbp++)
                ldsm4(Bf[nbp], base + REGB + (b_row + nbp * 16) * PITCH
                               + ks * 32 + b_colb);
#pragma unroll
            for (int mb = 0; mb < 4; mb++)
#pragma unroll
                for (int nb = 0; nb < 4; nb++)
                    mma16816h(acc[mb][nb], Af[mb], &Bf[nb >> 1][(nb & 1) * 2]);
        }
        if (c + 3 < NCH) { issue(c + 3, (c + 3) & 3); CP_COMMIT; }
    }

    const int erow = m0 + wm * 64 + (lane >> 2);
    const int ecol = o0 + wn * 32 + (lane & 3) * 2;
    if (mode == 0) {
        const int which = o0 >> 10;     // 0=q 1=k 2=v
        const float qs = 0.125f * 1.44269504088896340736f;
        __half* dstb = (which == 0) ? g_q : (which == 1) ? g_k : g_v;
        const float sc = (which == 0) ? qs : 1.0f;
#pragma unroll
        for (int mb = 0; mb < 4; mb++) {
            const int m = erow + mb * 16;
            const int bb = m >> 10, n = m & 1023;
#pragma unroll
            for (int nb = 0; nb < 4; nb++) {
                const int o = ecol + nb * 8;
                const int h = (o & 1023) >> 6;
                const int d = o & 63;
                size_t base = ((size_t)(bb * Hn + h) * Nseq + n) * Dh + d;
                *(uint32_t*)(dstb + base)          = packh2(acc[mb][nb][0] * sc,
                                                            acc[mb][nb][1] * sc);
                *(uint32_t*)(dstb + base + 8 * Dh) = packh2(acc[mb][nb][2] * sc,
                                                            acc[mb][nb][3] * sc);
            }
        }
    } else {
#pragma unroll
        for (int mb = 0; mb < 4; mb++) {
            const int m = erow + mb * 16;
#pragma unroll
            for (int nb = 0; nb < 4; nb++) {
                const int o = ecol + nb * 8;
                const float2 bv = *(const float2*)(bias + o);
                float* dst = out + (size_t)m * Cdim + o;
                *(float2*)dst = make_float2(acc[mb][nb][0] + bv.x,
                                            acc[mb][nb][1] + bv.y);
                *(float2*)(dst + 8 * Cdim) = make_float2(acc[mb][nb][2] + bv.x,
                                                         acc[mb][nb][3] + bv.y);
            }
        }
    }
}

// ---------------------------------------------------------------------------
// Flash attention, single fp16: S = Q*K^T (1 pass), O += P*V (1 pass).
// CTA: 128 Q rows x one (b,h), 8 warps, KV in 64-row tiles, 2-stage cp.async.
// smem 55KB -> 2 CTAs/SM. Epilogue: ao single fp16.
// ---------------------------------------------------------------------------
#define APITCH 144
#define AQREG  (128 * APITCH)            // 18432 (one Q matrix)
#define AKREG  (64 * APITCH)             // 9216 per KV matrix
#define AKV0   AQREG
#define ASTAGE (2 * AKREG)               // K, V = 18432
#define ATTN_SMEM (AQREG + 2 * ASTAGE)   // 55296

__global__ __launch_bounds__(256, 2) void attn_f16() {
    extern __shared__ char smem[];
    const uint32_t sb = s2u(smem);
    const int tid = threadIdx.x;
    const int w = tid >> 5, lane = tid & 31;
    const int bh = blockIdx.x;
    const int qb = blockIdx.y;

    const size_t hoff = (size_t)bh * (Nseq * Dh);
    const __half* qp = g_q + hoff + (size_t)qb * 128 * Dh;

    auto loadQ = [&]() {
#pragma unroll
        for (int j = 0; j < 4; j++) {
            int idx = j * 256 + tid;          // 0..1023
            int r   = (idx >> 3) & 127;
            int c8  = idx & 7;
            cpa16(sb + r * APITCH + c8 * 16, qp + r * Dh + c8 * 8);
        }
    };
    auto loadKV = [&](int kb, int st) {     // kb: 64-row block 0..15
        const size_t koff = hoff + (size_t)kb * 64 * Dh;
        const __half* srcs[2] = {g_k + koff, g_v + koff};
        uint32_t base = sb + AKV0 + st * ASTAGE;
#pragma unroll
        for (int j = 0; j < 4; j++) {
            int idx = j * 256 + tid;          // 0..1023
            int mt  = idx >> 9;               // 0=K 1=V
            int r   = (idx >> 3) & 63;
            int c8  = idx & 7;
            cpa16(base + mt * AKREG + r * APITCH + c8 * 16,
                  srcs[mt] + r * Dh + c8 * 8);
        }
    };

    loadQ();          CP_COMMIT;
    loadKV(0, 0);     CP_COMMIT;
    loadKV(1, 1);     CP_COMMIT;

    const int a_rowb = (w * 16 + (lane & 15)) * APITCH + (lane >> 4) * 16;
    const int k_rowi = ((lane >> 4) << 3) + (lane & 7);
    const int k_colb = ((lane >> 3) & 1) * 16;
    const int v_rowi = (lane & 7) + ((lane >> 3) & 1) * 8;
    const int v_colb = (lane >> 4) * 16;

    CP_WAIT(2);
    __syncthreads();

    uint32_t QA[4][4];
#pragma unroll
    for (int kc = 0; kc < 4; kc++)
        ldsm4(QA[kc], sb + a_rowb + kc * 32);

    float O[8][4];
#pragma unroll
    for (int i = 0; i < 8; i++)
#pragma unroll
        for (int j = 0; j < 4; j++) O[i][j] = 0.0f;
    float m0 = -1e30f, m1 = -1e30f;
    float l0 = 0.0f, l1 = 0.0f;

    for (int kb = 0; kb < 16; kb++) {
        if (kb + 1 < 16) { CP_WAIT(1); } else { CP_WAIT(0); }
        __syncthreads();
        const uint32_t kbase = sb + AKV0 + (kb & 1) * ASTAGE;

        // ----- S = Q K^T (1 pass), 64 cols -------------------------------
        float S[8][4];
#pragma unroll
        for (int i = 0; i < 8; i++)
#pragma unroll
            for (int j = 0; j < 4; j++) S[i][j] = 0.0f;

#pragma unroll
        for (int ng = 0; ng < 4; ng++) {
#pragma unroll
            for (int kc = 0; kc < 4; kc++) {
                uint32_t kf[4];
                ldsm4(kf, kbase + (ng * 16 + k_rowi) * APITCH + k_colb + kc * 32);
#pragma unroll
                for (int half = 0; half < 2; half++)
                    mma16816h(S[ng * 2 + half], QA[kc], &kf[half * 2]);
            }
        }

        // ----- online softmax ---------------------------------------------
        float rm0 = -1e30f, rm1 = -1e30f;
#pragma unroll
        for (int i = 0; i < 8; i++) {
            rm0 = fmaxf(rm0, fmaxf(S[i][0], S[i][1]));
            rm1 = fmaxf(rm1, fmaxf(S[i][2], S[i][3]));
        }
        rm0 = fmaxf(rm0, __shfl_xor_sync(0xffffffffu, rm0, 1));
        rm0 = fmaxf(rm0, __shfl_xor_sync(0xffffffffu, rm0, 2));
        rm1 = fmaxf(rm1, __shfl_xor_sync(0xffffffffu, rm1, 1));
        rm1 = fmaxf(rm1, __shfl_xor_sync(0xffffffffu, rm1, 2));

        float mn0 = fmaxf(m0, rm0), mn1 = fmaxf(m1, rm1);
        float al0 = ex2(m0 - mn0),  al1 = ex2(m1 - mn1);
        m0 = mn0; m1 = mn1;
        l0 *= al0; l1 *= al1;
#pragma unroll
        for (int i = 0; i < 8; i++) {
            O[i][0] *= al0; O[i][1] *= al0;
            O[i][2] *= al1; O[i][3] *= al1;
        }
        float ps0 = 0.0f, ps1 = 0.0f;
#pragma unroll
        for (int i = 0; i < 8; i++) {
            S[i][0] = ex2(S[i][0] - mn0);
            S[i][1] = ex2(S[i][1] - mn0);
            S[i][2] = ex2(S[i][2] - mn1);
            S[i][3] = ex2(S[i][3] - mn1);
            ps0 += S[i][0] + S[i][1];
            ps1 += S[i][2] + S[i][3];
        }
        l0 += ps0; l1 += ps1;

        // ----- O += P V (1 pass) ------------------------------------------
#pragma unroll
        for (int kc2 = 0; kc2 < 4; kc2++) {
            uint32_t pf[4];
            pf[0] = packh2(S[2 * kc2][0],     S[2 * kc2][1]);
            pf[1] = packh2(S[2 * kc2][2],     S[2 * kc2][3]);
            pf[2] = packh2(S[2 * kc2 + 1][0], S[2 * kc2 + 1][1]);
            pf[3] = packh2(S[2 * kc2 + 1][2], S[2 * kc2 + 1][3]);
#pragma unroll
            for (int dg = 0; dg < 4; dg++) {
                uint32_t vf[4];
                ldsm4t(vf, kbase + AKREG
                           + (kc2 * 16 + v_rowi) * APITCH + v_colb + dg * 32);
#pragma unroll
                for (int half = 0; half < 2; half++)
                    mma16816h(O[dg * 2 + half], pf, &vf[half * 2]);
            }
        }

        __syncthreads();
        if (kb + 2 < 16) { loadKV(kb + 2, kb & 1); CP_COMMIT; }
    }

    // ----- finalize + write ao single fp16 ---------------------------------
    l0 += __shfl_xor_sync(0xffffffffu, l0, 1);
    l0 += __shfl_xor_sync(0xffffffffu, l0, 2);
    l1 += __shfl_xor_sync(0xffffffffu, l1, 1);
    l1 += __shfl_xor_sync(0xffffffffu, l1, 2);
    const float inv0 = 1.0f / l0, inv1 = 1.0f / l1;

    const int b = bh >> 4, h = bh & 15;
    const int n0 = qb * 128 + w * 16 + (lane >> 2);
#pragma unroll
    for (int nb = 0; nb < 8; nb++) {
        const int d = nb * 8 + (lane & 3) * 2;
        size_t base0 = ((size_t)(b * Nseq + n0) * Cdim) + h * Dh + d;
        size_t base1 = base0 + (size_t)8 * Cdim;
        *(uint32_t*)(g_ao + base0) = packh2(O[nb][0] * inv0, O[nb][1] * inv0);
        *(uint32_t*)(g_ao + base1) = packh2(O[nb][2] * inv1, O[nb][3] * inv1);
    }
}

// ---------------------------------------------------------------------------
extern "C" void kernel_launch(void* const* d_in, const int* in_sizes, int n_in,
                              void* d_out, int out_size) {
    const float* x      = (const float*)d_in[0];   // [8,1024,1024]
    const float* w_qkv  = (const float*)d_in[1];   // [3072,1024]
    const float* w_proj = (const float*)d_in[2];   // [1024,1024]
    const float* b_proj = (const float*)d_in[3];   // [1024]
    float* out = (float*)d_out;

    cudaFuncSetAttribute(gemm_f16,
                         cudaFuncAttributeMaxDynamicSharedMemorySize, GEMM_SMEM);
    cudaFuncSetAttribute(attn_f16,
                         cudaFuncAttributeMaxDynamicSharedMemorySize, ATTN_SMEM);

    {
        int n4 = X4 + WQ4 + WP4;
        cvt_all<<<(n4 + 255) / 256, 256>>>((const float4*)x,
                                           (const float4*)w_qkv,
                                           (const float4*)w_proj);
    }

    dim3 g1(OQKV / 128, Mrows / 128);              // (24, 64)
    gemm_f16<<<g1, 256, GEMM_SMEM>>>(0, nullptr, nullptr);

    dim3 g2(Bsz * Hn, Nseq / 128);                 // (128, 8)
    attn_f16<<<g2, 256, ATTN_SMEM>>>();

    dim3 g3(Cdim / 128, Mrows / 128);              // (8, 64)
    gemm_f16<<<g3, 256, GEMM_SMEM>>>(1, b_proj, out);
}

// round 13
// speedup vs baseline: 2.6044x; 1.4687x over previous
#include <cuda_runtime.h>
#include <cuda_fp16.h>
#include <math_constants.h>
#include <cstdint>

#define Bsz  8
#define Nseq 1024
#define Cdim 1024
#define Hn   16
#define Dh   64
#define Mrows (Bsz * Nseq)
#define OQKV 3072

// ---------------------------------------------------------------------------
// Device-global scratch (allocation-free rule) — all single fp16
// ---------------------------------------------------------------------------
__device__ __half g_x16[Mrows * Cdim];         // x
__device__ __half g_wq [OQKV * Cdim];          // w_qkv
__device__ __half g_wp [Cdim * Cdim];          // w_proj
__device__ __half g_ao [Mrows * Cdim];         // attention out
__device__ __half g_q  [Bsz * Hn * Nseq * Dh]; // q (pre-scaled)
__device__ __half g_k  [Bsz * Hn * Nseq * Dh];
__device__ __half g_v  [Bsz * Hn * Nseq * Dh];

// ---------------------------------------------------------------------------
// PTX helpers
// ---------------------------------------------------------------------------
__device__ __forceinline__ uint32_t s2u(const void* p) {
    uint32_t a;
    asm("{ .reg .u64 t; cvta.to.shared.u64 t, %1; cvt.u32.u64 %0, t; }"
        : "=r"(a) : "l"(p));
    return a;
}

__device__ __forceinline__ void ldsm4(uint32_t* r, uint32_t addr) {
    asm volatile("ldmatrix.sync.aligned.m8n8.x4.shared.b16 {%0,%1,%2,%3}, [%4];"
                 : "=r"(r[0]), "=r"(r[1]), "=r"(r[2]), "=r"(r[3]) : "r"(addr));
}

__device__ __forceinline__ void ldsm4t(uint32_t* r, uint32_t addr) {
    asm volatile("ldmatrix.sync.aligned.m8n8.x4.trans.shared.b16 {%0,%1,%2,%3}, [%4];"
                 : "=r"(r[0]), "=r"(r[1]), "=r"(r[2]), "=r"(r[3]) : "r"(addr));
}

__device__ __forceinline__ void mma16816h(float* c, const uint32_t* a,
                                          const uint32_t* b) {
    asm volatile(
        "mma.sync.aligned.m16n8k16.row.col.f32.f16.f16.f32 "
        "{%0,%1,%2,%3}, {%4,%5,%6,%7}, {%8,%9}, {%0,%1,%2,%3};"
        : "+f"(c[0]), "+f"(c[1]), "+f"(c[2]), "+f"(c[3])
        : "r"(a[0]), "r"(a[1]), "r"(a[2]), "r"(a[3]), "r"(b[0]), "r"(b[1]));
}

__device__ __forceinline__ void cpa16(uint32_t saddr, const void* g) {
    asm volatile("cp.async.cg.shared.global [%0], [%1], 16;"
                 :: "r"(saddr), "l"(g));
}
#define CP_COMMIT asm volatile("cp.async.commit_group;")
#define CP_WAIT(n) asm volatile("cp.async.wait_group %0;" :: "n"(n))

__device__ __forceinline__ float ex2(float x) {
    float r;
    asm("ex2.approx.ftz.f32 %0, %1;" : "=f"(r) : "f"(x));
    return r;
}

__device__ __forceinline__ uint32_t packh2(float a, float b) {
    __half2 p = __floats2half2_rn(a, b);
    return reinterpret_cast<uint32_t&>(p);
}

// ---------------------------------------------------------------------------
// Conversion pre-pass: everything -> single fp16 (one merged launch)
// ---------------------------------------------------------------------------
#define X4  ((Mrows * Cdim) / 4)
#define WQ4 ((OQKV * Cdim) / 4)
#define WP4 ((Cdim * Cdim) / 4)

__global__ __launch_bounds__(256) void cvt_all(const float4* __restrict__ x,
                                               const float4* __restrict__ wq,
                                               const float4* __restrict__ wp) {
    int i = blockIdx.x * blockDim.x + threadIdx.x;
    const float4* in;
    __half* dst;
    int j;
    if (i < X4)                  { in = x;  dst = g_x16; j = i; }
    else if (i < X4 + WQ4)       { in = wq; dst = g_wq;  j = i - X4; }
    else if (i < X4 + WQ4 + WP4) { in = wp; dst = g_wp;  j = i - X4 - WQ4; }
    else return;
    float4 v = in[j];
    uint2 H;
    H.x = packh2(v.x, v.y);
    H.y = packh2(v.z, v.w);
    ((uint2*)dst)[j] = H;
}

// ---------------------------------------------------------------------------
// fp16 single-pass GEMM with explicit fragment double-buffering.
// CTA 128x128, 8 warps (64x32), KC=64 (4 ks sub-steps), 3-stage cp.async,
// 1 CTA/SM (reg headroom for frag pipeline). One barrier per chunk.
// mode 0: scatter q/k/v fp16 (q pre-scaled);  mode 1: +bias -> fp32 out.
// ---------------------------------------------------------------------------
#define KC    64
#define PITCH 144                      // 128B data + 16B pad, ldsm conflict-free
#define REGB  (128 * PITCH)            // 18432
#define GBUFB (2 * REGB)               // A, B = 36864 per stage
#define NSTAGE 3
#define GEMM_SMEM (NSTAGE * GBUFB)     // 110592

__global__ __launch_bounds__(256, 1) void gemm_f16(int mode,
                                                   const float* __restrict__ bias,
                                                   float* __restrict__ out) {
    extern __shared__ char smem[];
    const uint32_t sb = s2u(smem);
    const int tid = threadIdx.x;
    const int m0 = blockIdx.y * 128;
    const int o0 = blockIdx.x * 128;

    const __half* srcs[2] = {
        ((mode == 0) ? g_x16 : g_ao) + (size_t)m0 * Cdim,
        ((mode == 0) ? g_wq  : g_wp) + (size_t)o0 * Cdim};

    // per chunk: 2 matrices x 128 rows x 128B = 2048 cpa16 / 256 thr = 8 each
    auto issue = [&](int c, int stage) {
        uint32_t s0 = sb + stage * GBUFB;
        const int ko = c * KC;
#pragma unroll
        for (int j = 0; j < 8; j++) {
            int idx = j * 256 + tid;      // 0..2047
            int mt  = idx >> 10;
            int r   = (idx >> 3) & 127;
            int c8  = idx & 7;
            cpa16(s0 + mt * REGB + r * PITCH + c8 * 16,
                  srcs[mt] + r * Cdim + ko + c8 * 8);
        }
    };

    const int wid = tid >> 5, lane = tid & 31;
    const int wm = wid >> 2;
    const int wn = wid & 3;

    const int a_row  = wm * 64 + (lane & 15);
    const int a_colb = (lane >> 4) * 16;
    const int b_row  = wn * 32 + ((lane >> 4) << 3) + (lane & 7);
    const int b_colb = ((lane >> 3) & 1) * 16;

    float acc[4][4][4];
#pragma unroll
    for (int i = 0; i < 4; i++)
#pragma unroll
        for (int j = 0; j < 4; j++)
#pragma unroll
            for (int k = 0; k < 4; k++) acc[i][j][k] = 0.0f;

    issue(0, 0); CP_COMMIT;
    issue(1, 1); CP_COMMIT;

    uint32_t Af[2][4][4], Bf[2][2][4];

    auto loadfrags = [&](int buf, uint32_t base, int ks) {
#pragma unroll
        for (int mb = 0; mb < 4; mb++)
            ldsm4(Af[buf][mb],
                  base + (a_row + mb * 16) * PITCH + ks * 32 + a_colb);
#pragma unroll
        for (int nbp = 0; nbp < 2; nbp++)
            ldsm4(Bf[buf][nbp],
                  base + REGB + (b_row + nbp * 16) * PITCH + ks * 32 + b_colb);
    };
    auto do_mma = [&](int buf) {
#pragma unroll
        for (int mb = 0; mb < 4; mb++)
#pragma unroll
            for (int nb = 0; nb < 4; nb++)
                mma16816h(acc[mb][nb], Af[buf][mb],
                          &Bf[buf][nb >> 1][(nb & 1) * 2]);
    };

    const int NCH = Cdim / KC;   // 16
    for (int c = 0; c < NCH; c++) {
        if (c + 1 < NCH) { CP_WAIT(1); } else { CP_WAIT(0); }
        __syncthreads();

        const uint32_t base = sb + (c % NSTAGE) * GBUFB;
        loadfrags(0, base, 0);
#pragma unroll
        for (int ks = 0; ks < 4; ks++) {
            const int cur = ks & 1;
            if (ks < 3) loadfrags(cur ^ 1, base, ks + 1);
            do_mma(cur);
        }
        // stage (c+2)%3 == (c-1)%3: its reads finished before this chunk's
        // barrier -> safe to refill now, no trailing barrier.
        if (c + 2 < NCH) { issue(c + 2, (c + 2) % NSTAGE); CP_COMMIT; }
    }

    const int erow = m0 + wm * 64 + (lane >> 2);
    const int ecol = o0 + wn * 32 + (lane & 3) * 2;
    if (mode == 0) {
        const int which = o0 >> 10;     // 0=q 1=k 2=v
        const float qs = 0.125f * 1.44269504088896340736f;
        __half* dstb = (which == 0) ? g_q : (which == 1) ? g_k : g_v;
        const float sc = (which == 0) ? qs : 1.0f;
#pragma unroll
        for (int mb = 0; mb < 4; mb++) {
            const int m = erow + mb * 16;
            const int bb = m >> 10, n = m & 1023;
#pragma unroll
            for (int nb = 0; nb < 4; nb++) {
                const int o = ecol + nb * 8;
                const int h = (o & 1023) >> 6;
                const int d = o & 63;
                size_t base = ((size_t)(bb * Hn + h) * Nseq + n) * Dh + d;
                *(uint32_t*)(dstb + base)          = packh2(acc[mb][nb][0] * sc,
                                                            acc[mb][nb][1] * sc);
                *(uint32_t*)(dstb + base + 8 * Dh) = packh2(acc[mb][nb][2] * sc,
                                                            acc[mb][nb][3] * sc);
            }
        }
    } else {
#pragma unroll
        for (int mb = 0; mb < 4; mb++) {
            const int m = erow + mb * 16;
#pragma unroll
            for (int nb = 0; nb < 4; nb++) {
                const int o = ecol + nb * 8;
                const float2 bv = *(const float2*)(bias + o);
                float* dst = out + (size_t)m * Cdim + o;
                *(float2*)dst = make_float2(acc[mb][nb][0] + bv.x,
                                            acc[mb][nb][1] + bv.y);
                *(float2*)(dst + 8 * Cdim) = make_float2(acc[mb][nb][2] + bv.x,
                                                         acc[mb][nb][3] + bv.y);
            }
        }
    }
}

// ---------------------------------------------------------------------------
// Flash attention, single fp16 (unchanged from R12): S = Q*K^T, O += P*V.
// CTA: 128 Q rows x one (b,h), 8 warps, KV in 64-row tiles, 2-stage cp.async.
// smem 55KB -> 2 CTAs/SM. Epilogue: ao single fp16.
// ---------------------------------------------------------------------------
#define APITCH 144
#define AQREG  (128 * APITCH)            // 18432 (one Q matrix)
#define AKREG  (64 * APITCH)             // 9216 per KV matrix
#define AKV0   AQREG
#define ASTAGE (2 * AKREG)               // K, V = 18432
#define ATTN_SMEM (AQREG + 2 * ASTAGE)   // 55296

__global__ __launch_bounds__(256, 2) void attn_f16() {
    extern __shared__ char smem[];
    const uint32_t sb = s2u(smem);
    const int tid = threadIdx.x;
    const int w = tid >> 5, lane = tid & 31;
    const int bh = blockIdx.x;
    const int qb = blockIdx.y;

    const size_t hoff = (size_t)bh * (Nseq * Dh);
    const __half* qp = g_q + hoff + (size_t)qb * 128 * Dh;

    auto loadQ = [&]() {
#pragma unroll
        for (int j = 0; j < 4; j++) {
            int idx = j * 256 + tid;          // 0..1023
            int r   = (idx >> 3) & 127;
            int c8  = idx & 7;
            cpa16(sb + r * APITCH + c8 * 16, qp + r * Dh + c8 * 8);
        }
    };
    auto loadKV = [&](int kb, int st) {     // kb: 64-row block 0..15
        const size_t koff = hoff + (size_t)kb * 64 * Dh;
        const __half* srcs[2] = {g_k + koff, g_v + koff};
        uint32_t base = sb + AKV0 + st * ASTAGE;
#pragma unroll
        for (int j = 0; j < 4; j++) {
            int idx = j * 256 + tid;          // 0..1023
            int mt  = idx >> 9;               // 0=K 1=V
            int r   = (idx >> 3) & 63;
            int c8  = idx & 7;
            cpa16(base + mt * AKREG + r * APITCH + c8 * 16,
                  srcs[mt] + r * Dh + c8 * 8);
        }
    };

    loadQ();          CP_COMMIT;
    loadKV(0, 0);     CP_COMMIT;
    loadKV(1, 1);     CP_COMMIT;

    const int a_rowb = (w * 16 + (lane & 15)) * APITCH + (lane >> 4) * 16;
    const int k_rowi = ((lane >> 4) << 3) + (lane & 7);
    const int k_colb = ((lane >> 3) & 1) * 16;
    const int v_rowi = (lane & 7) + ((lane >> 3) & 1) * 8;
    const int v_colb = (lane >> 4) * 16;

    CP_WAIT(2);
    __syncthreads();

    uint32_t QA[4][4];
#pragma unroll
    for (int kc = 0; kc < 4; kc++)
        ldsm4(QA[kc], sb + a_rowb + kc * 32);

    float O[8][4];
#pragma unroll
    for (int i = 0; i < 8; i++)
#pragma unroll
        for (int j = 0; j < 4; j++) O[i][j] = 0.0f;
    float m0 = -1e30f, m1 = -1e30f;
    float l0 = 0.0f, l1 = 0.0f;

    for (int kb = 0; kb < 16; kb++) {
        if (kb + 1 < 16) { CP_WAIT(1); } else { CP_WAIT(0); }
        __syncthreads();
        const uint32_t kbase = sb + AKV0 + (kb & 1) * ASTAGE;

        float S[8][4];
#pragma unroll
        for (int i = 0; i < 8; i++)
#pragma unroll
            for (int j = 0; j < 4; j++) S[i][j] = 0.0f;

#pragma unroll
        for (int ng = 0; ng < 4; ng++) {
#pragma unroll
            for (int kc = 0; kc < 4; kc++) {
                uint32_t kf[4];
                ldsm4(kf, kbase + (ng * 16 + k_rowi) * APITCH + k_colb + kc * 32);
#pragma unroll
                for (int half = 0; half < 2; half++)
                    mma16816h(S[ng * 2 + half], QA[kc], &kf[half * 2]);
            }
        }

        float rm0 = -1e30f, rm1 = -1e30f;
#pragma unroll
        for (int i = 0; i < 8; i++) {
            rm0 = fmaxf(rm0, fmaxf(S[i][0], S[i][1]));
            rm1 = fmaxf(rm1, fmaxf(S[i][2], S[i][3]));
        }
        rm0 = fmaxf(rm0, __shfl_xor_sync(0xffffffffu, rm0, 1));
        rm0 = fmaxf(rm0, __shfl_xor_sync(0xffffffffu, rm0, 2));
        rm1 = fmaxf(rm1, __shfl_xor_sync(0xffffffffu, rm1, 1));
        rm1 = fmaxf(rm1, __shfl_xor_sync(0xffffffffu, rm1, 2));

        float mn0 = fmaxf(m0, rm0), mn1 = fmaxf(m1, rm1);
        float al0 = ex2(m0 - mn0),  al1 = ex2(m1 - mn1);
        m0 = mn0; m1 = mn1;
        l0 *= al0; l1 *= al1;
#pragma unroll
        for (int i = 0; i < 8; i++) {
            O[i][0] *= al0; O[i][1] *= al0;
            O[i][2] *= al1; O[i][3] *= al1;
        }
        float ps0 = 0.0f, ps1 = 0.0f;
#pragma unroll
        for (int i = 0; i < 8; i++) {
            S[i][0] = ex2(S[i][0] - mn0);
            S[i][1] = ex2(S[i][1] - mn0);
            S[i][2] = ex2(S[i][2] - mn1);
            S[i][3] = ex2(S[i][3] - mn1);
            ps0 += S[i][0] + S[i][1];
            ps1 += S[i][2] + S[i][3];
        }
        l0 += ps0; l1 += ps1;

#pragma unroll
        for (int kc2 = 0; kc2 < 4; kc2++) {
            uint32_t pf[4];
            pf[0] = packh2(S[2 * kc2][0],     S[2 * kc2][1]);
            pf[1] = packh2(S[2 * kc2][2],     S[2 * kc2][3]);
            pf[2] = packh2(S[2 * kc2 + 1][0], S[2 * kc2 + 1][1]);
            pf[3] = packh2(S[2 * kc2 + 1][2], S[2 * kc2 + 1][3]);
#pragma unroll
            for (int dg = 0; dg < 4; dg++) {
                uint32_t vf[4];
                ldsm4t(vf, kbase + AKREG
                           + (kc2 * 16 + v_rowi) * APITCH + v_colb + dg * 32);
#pragma unroll
                for (int half = 0; half < 2; half++)
                    mma16816h(O[dg * 2 + half], pf, &vf[half * 2]);
            }
        }

        __syncthreads();
        if (kb + 2 < 16) { loadKV(kb + 2, kb & 1); CP_COMMIT; }
    }

    l0 += __shfl_xor_sync(0xffffffffu, l0, 1);
    l0 += __shfl_xor_sync(0xffffffffu, l0, 2);
    l1 += __shfl_xor_sync(0xffffffffu, l1, 1);
    l1 += __shfl_xor_sync(0xffffffffu, l1, 2);
    const float inv0 = 1.0f / l0, inv1 = 1.0f / l1;

    const int b = bh >> 4, h = bh & 15;
    const int n0 = qb * 128 + w * 16 + (lane >> 2);
#pragma unroll
    for (int nb = 0; nb < 8; nb++) {
        const int d = nb * 8 + (lane & 3) * 2;
        size_t base0 = ((size_t)(b * Nseq + n0) * Cdim) + h * Dh + d;
        size_t base1 = base0 + (size_t)8 * Cdim;
        *(uint32_t*)(g_ao + base0) = packh2(O[nb][0] * inv0, O[nb][1] * inv0);
        *(uint32_t*)(g_ao + base1) = packh2(O[nb][2] * inv1, O[nb][3] * inv1);
    }
}

// ---------------------------------------------------------------------------
extern "C" void kernel_launch(void* const* d_in, const int* in_sizes, int n_in,
                              void* d_out, int out_size) {
    const float* x      = (const float*)d_in[0];   // [8,1024,1024]
    const float* w_qkv  = (const float*)d_in[1];   // [3072,1024]
    const float* w_proj = (const float*)d_in[2];   // [1024,1024]
    const float* b_proj = (const float*)d_in[3];   // [1024]
    float* out = (float*)d_out;

    cudaFuncSetAttribute(gemm_f16,
                         cudaFuncAttributeMaxDynamicSharedMemorySize, GEMM_SMEM);
    cudaFuncSetAttribute(attn_f16,
                         cudaFuncAttributeMaxDynamicSharedMemorySize, ATTN_SMEM);

    {
        int n4 = X4 + WQ4 + WP4;
        cvt_all<<<(n4 + 255) / 256, 256>>>((const float4*)x,
                                           (const float4*)w_qkv,
                                           (const float4*)w_proj);
    }

    dim3 g1(OQKV / 128, Mrows / 128);              // (24, 64)
    gemm_f16<<<g1, 256, GEMM_SMEM>>>(0, nullptr, nullptr);

    dim3 g2(Bsz * Hn, Nseq / 128);                 // (128, 8)
    attn_f16<<<g2, 256, ATTN_SMEM>>>();

    dim3 g3(Cdim / 128, Mrows / 128);              // (8, 64)
    gemm_f16<<<g3, 256, GEMM_SMEM>>>(1, b_proj, out);
}